// round 5
// baseline (speedup 1.0000x reference)
#include <cuda_runtime.h>
#include <cuda_bf16.h>
#include <cstdint>

typedef unsigned long long u64;
typedef unsigned int u32;

// ---------------- scratch ----------------
__device__ float g_pre_ox[512 * 64];
__device__ float g_pre_tp[512 * 64];
__device__ float g_pts[512 * 1000 * 2];
__device__ float g_targets[512 * 1000 * 2];
__device__ float g_off_part[512 * 4];
__device__ float g_cls[512];
__device__ float g_endsum[512];

// ---------------- packed f32x2 helpers ----------------
__device__ __forceinline__ u64 F2(float a, float b) {
    u64 r; asm("mov.b64 %0,{%1,%2};" : "=l"(r) : "f"(a), "f"(b)); return r;
}
__device__ __forceinline__ void UNPK(u64 v, float& a, float& b) {
    asm("mov.b64 {%0,%1},%2;" : "=f"(a), "=f"(b) : "l"(v));
}
__device__ __forceinline__ u64 FMA2(u64 a, u64 b, u64 c) {
    u64 d; asm("fma.rn.f32x2 %0,%1,%2,%3;" : "=l"(d) : "l"(a), "l"(b), "l"(c)); return d;
}
__device__ __forceinline__ u64 ADD2(u64 a, u64 b) {
    u64 d; asm("add.rn.f32x2 %0,%1,%2;" : "=l"(d) : "l"(a), "l"(b)); return d;
}
__device__ __forceinline__ u64 MUL2(u64 a, u64 b) {
    u64 d; asm("mul.rn.f32x2 %0,%1,%2;" : "=l"(d) : "l"(a), "l"(b)); return d;
}
__device__ __forceinline__ u64 LD2(const float* p) {
    return *reinterpret_cast<const u64*>(p);
}

__device__ __forceinline__ float sl1(float z) {
    float d = fabsf(z);
    return d < 1.0f ? 0.5f * d * d : d - 0.5f;
}

// Branchless exact-GELU (A&S 7.1.26 erfc, |err|<=1.5e-7)
__device__ __forceinline__ float fast_gelu(float z) {
    float az = fabsf(z);
    float u = 0.70710678118654752f * az;
    float t;
    asm("rcp.approx.f32 %0, %1;" : "=f"(t) : "f"(fmaf(0.3275911f, u, 1.0f)));
    float e;
    asm("ex2.approx.f32 %0, %1;" : "=f"(e) : "f"(u * u * -1.4426950408889634f));
    float p = fmaf(1.061405429f, t, -1.453152027f);
    p = fmaf(p, t, 1.421413741f);
    p = fmaf(p, t, -0.284496736f);
    p = fmaf(p, t, 0.254829592f);
    float q = p * t * e;
    return fmaf(-0.5f * az, q, fmaxf(z, 0.0f));
}

__device__ __forceinline__ u32 tf32_rna(float x) {
    u32 r; asm("cvt.rna.tf32.f32 %0, %1;" : "=r"(r) : "f"(x)); return r;
}
__device__ __forceinline__ void mma8(float* c, const u32* a, u32 b0, u32 b1) {
    asm volatile(
        "mma.sync.aligned.m16n8k8.row.col.f32.tf32.tf32.f32 "
        "{%0,%1,%2,%3},{%4,%5,%6,%7},{%8,%9},{%0,%1,%2,%3};"
        : "+f"(c[0]), "+f"(c[1]), "+f"(c[2]), "+f"(c[3])
        : "r"(a[0]), "r"(a[1]), "r"(a[2]), "r"(a[3]), "r"(b0), "r"(b1));
}

__device__ __forceinline__ float qsum(float v) {
    v += __shfl_xor_sync(0xffffffffu, v, 1);
    v += __shfl_xor_sync(0xffffffffu, v, 2);
    return v;
}
__device__ __forceinline__ float wsum(float v) {
#pragma unroll
    for (int o = 16; o; o >>= 1) v += __shfl_xor_sync(0xffffffffu, v, o);
    return v;
}

// LN (eps 1e-5) + GELU on two fragment rows (8 u64 pairs = 16 cols per lane each),
// row stats via quad shuffles. gp/bep are pair-permuted tables indexed 8*kt+2*tig.
__device__ __forceinline__ void ln_gelu_frag(u64* hA, u64* hB,
                                             const float* gp, const float* bep, int tig) {
    u64 sa = hA[0], sb = hB[0];
#pragma unroll
    for (int kt = 1; kt < 8; kt++) { sa = ADD2(sa, hA[kt]); sb = ADD2(sb, hB[kt]); }
    float a0, a1, b0, b1; UNPK(sa, a0, a1); UNPK(sb, b0, b1);
    float mA = qsum(a0 + a1) * 0.015625f;
    float mB = qsum(b0 + b1) * 0.015625f;
    u64 mA2 = F2(-mA, -mA), mB2 = F2(-mB, -mB);
    u64 qa = F2(0.f, 0.f), qb = F2(0.f, 0.f);
#pragma unroll
    for (int kt = 0; kt < 8; kt++) {
        hA[kt] = ADD2(hA[kt], mA2); qa = FMA2(hA[kt], hA[kt], qa);
        hB[kt] = ADD2(hB[kt], mB2); qb = FMA2(hB[kt], hB[kt], qb);
    }
    UNPK(qa, a0, a1); UNPK(qb, b0, b1);
    float rA = rsqrtf(qsum(a0 + a1) * 0.015625f + 1e-5f);
    float rB = rsqrtf(qsum(b0 + b1) * 0.015625f + 1e-5f);
    u64 rA2 = F2(rA, rA), rB2 = F2(rB, rB);
#pragma unroll
    for (int kt = 0; kt < 8; kt++) {
        int o = 8 * kt + 2 * tig;
        u64 g2 = LD2(&gp[o]), be2 = LD2(&bep[o]);
        u64 zA = FMA2(MUL2(hA[kt], rA2), g2, be2);
        u64 zB = FMA2(MUL2(hB[kt], rB2), g2, be2);
        float z0, z1; UNPK(zA, z0, z1);
        hA[kt] = F2(fast_gelu(z0), fast_gelu(z1));
        UNPK(zB, z0, z1);
        hB[kt] = F2(fast_gelu(z0), fast_gelu(z1));
    }
}

// ---------------- K0: per-batch precompute (4-way k-split) ----------------
__global__ void __launch_bounds__(256) precompute_kernel(
    const float* __restrict__ at, const float* __restrict__ vf,
    const float* __restrict__ ox_w1, const float* __restrict__ ox_b1,
    const float* __restrict__ tp_w1, const float* __restrict__ tp_b1) {
    __shared__ float s_vf[64], s_at[64];
    __shared__ float pa[4][64], pt[4][64];
    int b = blockIdx.x, tid = threadIdx.x;
    int c = tid & 63, kq = tid >> 6;
    if (tid < 64) { s_vf[tid] = vf[b * 64 + tid]; s_at[tid] = at[b * 64 + tid]; }
    __syncthreads();
    float a = 0.f, t = 0.f;
#pragma unroll
    for (int k = kq * 16; k < kq * 16 + 16; k++) {
        a += s_vf[k] * ox_w1[k * 64 + c] + s_at[k] * ox_w1[(64 + k) * 64 + c];
        t += s_vf[k] * tp_w1[k * 64 + c] + s_at[k] * tp_w1[(64 + k) * 64 + c];
    }
    pa[kq][c] = a; pt[kq][c] = t;
    __syncthreads();
    if (tid < 64) {
        g_pre_ox[b * 64 + tid] = pa[0][tid] + pa[1][tid] + pa[2][tid] + pa[3][tid] + ox_b1[tid];
        g_pre_tp[b * 64 + tid] = pt[0][tid] + pt[1][tid] + pt[2][tid] + pt[3][tid] + tp_b1[tid];
    }
}

// ---------------- K1: top-1000 selection (bitonic 2048) ----------------
__global__ void __launch_bounds__(1024) select_kernel(const float* __restrict__ osm) {
    __shared__ u64 s[2048];
    int b = blockIdx.x, t = threadIdx.x;
#pragma unroll
    for (int m = t; m < 2048; m += 1024) {
        u64 key;
        if (m < 2000) {
            float x = osm[(b * 2000 + m) * 4];
            float y = osm[(b * 2000 + m) * 4 + 1];
            float d2 = x * x + y * y;
            key = ((u64)__float_as_uint(d2) << 32) | (u32)m;
        } else key = ~0ull;
        s[m] = key;
    }
    bool lastBig = true;
    for (int k = 2; k <= 2048; k <<= 1) {
        for (int j = k >> 1; j > 0; j >>= 1) {
            bool big = (j >= 64);
            if (big || lastBig) __syncthreads(); else __syncwarp();
            int i0 = ((t & ~(j - 1)) << 1) | (t & (j - 1));
            int i1 = i0 | j;
            bool up = ((i0 & k) == 0);
            u64 A = s[i0], B = s[i1];
            if ((A > B) == up) { s[i0] = B; s[i1] = A; }
            lastBig = big;
        }
    }
    __syncthreads();
    if (t < 1000) {
        u32 m = (u32)(s[t] & 0xffffffffull);
        g_pts[(b * 1000 + t) * 2]     = osm[(b * 2000 + m) * 4];
        g_pts[(b * 1000 + t) * 2 + 1] = osm[(b * 2000 + m) * 4 + 1];
    }
}

// ---------------- K2: per-point MLP, fragment-native, barrier-free mainloop ----------------
#define WSTR 136
#define MLP_DSMEM (64 * WSTR * 4)

// pair-permuted table indices
#define T_PRE_OX 0
#define T_OXX    1
#define T_OXY    2
#define T_OXG    3
#define T_OXBE   4
#define T_W2A    5
#define T_W2B    6
#define T_PRE_TP 7
#define T_TPX    8
#define T_TPY    9
#define T_G1     10
#define T_BE1    11

__global__ void __launch_bounds__(256, 2) mlp_kernel(
    const float* __restrict__ ox_w1, const float* __restrict__ ox_g1, const float* __restrict__ ox_be1,
    const float* __restrict__ ox_w2, const float* __restrict__ ox_b2,
    const float* __restrict__ tp_w1, const float* __restrict__ tp_g1, const float* __restrict__ tp_be1,
    const float* __restrict__ tp_w2, const float* __restrict__ tp_b2,
    const float* __restrict__ tp_g2, const float* __restrict__ tp_be2,
    const float* __restrict__ tp_w3, const float* __restrict__ tp_b3,
    const float* __restrict__ end) {
    extern __shared__ float w2i[];   // [64][WSTR], (hi,lo) interleaved per element
    __shared__ __align__(16) float P[12][64];
    __shared__ __align__(16) float s_b2[64], s_g2[64], s_be2[64], s_w3[128];
    __shared__ float s_red[256];

    int b = blockIdx.y;
    int tid = threadIdx.x;

    if (tid < 64) { s_b2[tid] = tp_b2[tid]; s_g2[tid] = tp_g2[tid]; s_be2[tid] = tp_be2[tid]; }
    if (tid < 128) s_w3[tid] = tp_w3[tid];
    if (tid < 32) {
        int c0 = (tid >> 2) * 8 + (tid & 3), c1 = c0 + 4;
        int o = 2 * tid;
        P[T_PRE_OX][o] = g_pre_ox[b * 64 + c0]; P[T_PRE_OX][o + 1] = g_pre_ox[b * 64 + c1];
        P[T_PRE_TP][o] = g_pre_tp[b * 64 + c0]; P[T_PRE_TP][o + 1] = g_pre_tp[b * 64 + c1];
        P[T_OXX][o] = ox_w1[128 * 64 + c0];     P[T_OXX][o + 1] = ox_w1[128 * 64 + c1];
        P[T_OXY][o] = ox_w1[129 * 64 + c0];     P[T_OXY][o + 1] = ox_w1[129 * 64 + c1];
        P[T_TPX][o] = tp_w1[128 * 64 + c0];     P[T_TPX][o + 1] = tp_w1[128 * 64 + c1];
        P[T_TPY][o] = tp_w1[129 * 64 + c0];     P[T_TPY][o + 1] = tp_w1[129 * 64 + c1];
        P[T_OXG][o] = ox_g1[c0];                P[T_OXG][o + 1] = ox_g1[c1];
        P[T_OXBE][o] = ox_be1[c0];              P[T_OXBE][o + 1] = ox_be1[c1];
        P[T_G1][o] = tp_g1[c0];                 P[T_G1][o + 1] = tp_g1[c1];
        P[T_BE1][o] = tp_be1[c0];               P[T_BE1][o + 1] = tp_be1[c1];
        P[T_W2A][o] = ox_w2[2 * c0];            P[T_W2A][o + 1] = ox_w2[2 * c1];
        P[T_W2B][o] = ox_w2[2 * c0 + 1];        P[T_W2B][o + 1] = ox_w2[2 * c1 + 1];
    }
    // W2 -> tf32 (hi,lo) interleaved
    for (int i = tid; i < 4096; i += 256) {
        float w = tp_w2[i];
        u32 hb = tf32_rna(w);
        float hif = __uint_as_float(hb);
        float lof = __uint_as_float(tf32_rna(w - hif));
        int k = i >> 6, n = i & 63;
        *reinterpret_cast<u64*>(&w2i[k * WSTR + 2 * n]) = F2(hif, lof);
    }
    __syncthreads();

    int wid = tid >> 5, lane = tid & 31;
    int gid = lane >> 2, tig = lane & 3;
    float e0 = end[2 * b], e1 = end[2 * b + 1];
    float b2o0 = ox_b2[0], b2o1 = ox_b2[1];
    float b3_0 = tp_b3[0], b3_1 = tp_b3[1];
    float smAcc = 0.f;

#pragma unroll 1
    for (int mt = 0; mt < 2; mt++) {
        int iA = blockIdx.x * 256 + wid * 32 + mt * 16 + gid;
        int iB = iA + 8;
        float xA = 0.f, yA = 0.f, xB = 0.f, yB = 0.f;
        if (iA < 1000) { float2 v = *reinterpret_cast<const float2*>(&g_pts[(b * 1000 + iA) * 2]); xA = v.x; yA = v.y; }
        if (iB < 1000) { float2 v = *reinterpret_cast<const float2*>(&g_pts[(b * 1000 + iB) * 2]); xB = v.x; yB = v.y; }

        u64 hA[8], hB[8];
        // layer1-ox
        {
            u64 xA2 = F2(xA, xA), yA2 = F2(yA, yA), xB2 = F2(xB, xB), yB2 = F2(yB, yB);
#pragma unroll
            for (int kt = 0; kt < 8; kt++) {
                int o = 8 * kt + 2 * tig;
                u64 pre = LD2(&P[T_PRE_OX][o]), wx = LD2(&P[T_OXX][o]), wy = LD2(&P[T_OXY][o]);
                hA[kt] = FMA2(yA2, wy, FMA2(xA2, wx, pre));
                hB[kt] = FMA2(yB2, wy, FMA2(xB2, wx, pre));
            }
        }
        ln_gelu_frag(hA, hB, &P[T_OXG][0], &P[T_OXBE][0], tig);

        // offset head: (64->2) per row via quad reduction
        float txA, tyA, txB, tyB;
        {
            u64 axA = F2(0.f, 0.f), ayA = axA, axB = axA, ayB = axA;
#pragma unroll
            for (int kt = 0; kt < 8; kt++) {
                int o = 8 * kt + 2 * tig;
                u64 wa = LD2(&P[T_W2A][o]), wb = LD2(&P[T_W2B][o]);
                axA = FMA2(hA[kt], wa, axA); ayA = FMA2(hA[kt], wb, ayA);
                axB = FMA2(hB[kt], wa, axB); ayB = FMA2(hB[kt], wb, ayB);
            }
            float p0, p1;
            UNPK(axA, p0, p1); txA = xA + qsum(p0 + p1) + b2o0;
            UNPK(ayA, p0, p1); tyA = yA + qsum(p0 + p1) + b2o1;
            UNPK(axB, p0, p1); txB = xB + qsum(p0 + p1) + b2o0;
            UNPK(ayB, p0, p1); tyB = yB + qsum(p0 + p1) + b2o1;
        }

        // layer1-tp
        {
            u64 xA2 = F2(txA, txA), yA2 = F2(tyA, tyA), xB2 = F2(txB, txB), yB2 = F2(tyB, tyB);
#pragma unroll
            for (int kt = 0; kt < 8; kt++) {
                int o = 8 * kt + 2 * tig;
                u64 pre = LD2(&P[T_PRE_TP][o]), wx = LD2(&P[T_TPX][o]), wy = LD2(&P[T_TPY][o]);
                hA[kt] = FMA2(yA2, wy, FMA2(xA2, wx, pre));
                hB[kt] = FMA2(yB2, wy, FMA2(xB2, wx, pre));
            }
        }
        ln_gelu_frag(hA, hB, &P[T_G1][0], &P[T_BE1][0], tig);

        // GEMM: 16x64 @ 64x64, tf32 3-term
        float cst[8][4];
#pragma unroll
        for (int nt = 0; nt < 8; nt++)
#pragma unroll
            for (int qq = 0; qq < 4; qq++) cst[nt][qq] = 0.f;

#pragma unroll
        for (int kt = 0; kt < 8; kt++) {
            float a0, a2; UNPK(hA[kt], a0, a2);   // row gid: cols kc, kc+4
            float a1, a3; UNPK(hB[kt], a1, a3);   // row gid+8
            u32 ah[4], al[4];
            ah[0] = tf32_rna(a0); al[0] = tf32_rna(a0 - __uint_as_float(ah[0]));
            ah[1] = tf32_rna(a1); al[1] = tf32_rna(a1 - __uint_as_float(ah[1]));
            ah[2] = tf32_rna(a2); al[2] = tf32_rna(a2 - __uint_as_float(ah[2]));
            ah[3] = tf32_rna(a3); al[3] = tf32_rna(a3 - __uint_as_float(ah[3]));
            int kc = kt * 8 + tig;
            const float* r0p = &w2i[kc * WSTR];
            const float* r1p = &w2i[(kc + 4) * WSTR];
#pragma unroll
            for (int nt = 0; nt < 8; nt++) {
                int nc2 = 2 * (nt * 8 + gid);
                u64 w0 = LD2(r0p + nc2);
                u64 w1 = LD2(r1p + nc2);
                float f; u32 bh0, bl0, bh1, bl1;
                float fh, fl;
                UNPK(w0, fh, fl); bh0 = __float_as_uint(fh); bl0 = __float_as_uint(fl);
                UNPK(w1, fh, fl); bh1 = __float_as_uint(fh); bl1 = __float_as_uint(fl);
                (void)f;
                mma8(cst[nt], ah, bh0, bh1);
                mma8(cst[nt], ah, bl0, bl1);
                mma8(cst[nt], al, bh0, bh1);
            }
        }

        // epilogue: +bias, LN (quad shuffles), GELU, 64->2
        float sA = 0.f, sB = 0.f;
#pragma unroll
        for (int nt = 0; nt < 8; nt++) {
            int col0 = nt * 8 + 2 * tig, col1 = col0 + 1;
            cst[nt][0] += s_b2[col0]; cst[nt][1] += s_b2[col1];
            cst[nt][2] += s_b2[col0]; cst[nt][3] += s_b2[col1];
            sA += cst[nt][0] + cst[nt][1];
            sB += cst[nt][2] + cst[nt][3];
        }
        float mA = qsum(sA) * 0.015625f;
        float mB = qsum(sB) * 0.015625f;
        float qA = 0.f, qB = 0.f;
#pragma unroll
        for (int nt = 0; nt < 8; nt++) {
            float d0 = cst[nt][0] - mA, d1 = cst[nt][1] - mA;
            float d2 = cst[nt][2] - mB, d3 = cst[nt][3] - mB;
            qA += d0 * d0 + d1 * d1;
            qB += d2 * d2 + d3 * d3;
        }
        float rA = rsqrtf(qsum(qA) * 0.015625f + 1e-5f);
        float rB = rsqrtf(qsum(qB) * 0.015625f + 1e-5f);

        float pA0 = 0.f, pA1 = 0.f, pB0 = 0.f, pB1 = 0.f;
#pragma unroll
        for (int nt = 0; nt < 8; nt++) {
            int col0 = nt * 8 + 2 * tig, col1 = col0 + 1;
            float z;
            z = fast_gelu((cst[nt][0] - mA) * rA * s_g2[col0] + s_be2[col0]);
            pA0 += z * s_w3[2 * col0]; pA1 += z * s_w3[2 * col0 + 1];
            z = fast_gelu((cst[nt][1] - mA) * rA * s_g2[col1] + s_be2[col1]);
            pA0 += z * s_w3[2 * col1]; pA1 += z * s_w3[2 * col1 + 1];
            z = fast_gelu((cst[nt][2] - mB) * rB * s_g2[col0] + s_be2[col0]);
            pB0 += z * s_w3[2 * col0]; pB1 += z * s_w3[2 * col0 + 1];
            z = fast_gelu((cst[nt][3] - mB) * rB * s_g2[col1] + s_be2[col1]);
            pB0 += z * s_w3[2 * col1]; pB1 += z * s_w3[2 * col1 + 1];
        }
        pA0 = qsum(pA0); pA1 = qsum(pA1);
        pB0 = qsum(pB0); pB1 = qsum(pB1);

        if (tig == 0) {
            float tA0 = pA0 + b3_0, tA1 = pA1 + b3_1;
            float tB0 = pB0 + b3_0, tB1 = pB1 + b3_1;
            if (iA < 1000) {
                g_targets[(b * 1000 + iA) * 2]     = tA0;
                g_targets[(b * 1000 + iA) * 2 + 1] = tA1;
                smAcc += sl1(tA0 - e0) + sl1(tA1 - e1);
            }
            if (iB < 1000) {
                g_targets[(b * 1000 + iB) * 2]     = tB0;
                g_targets[(b * 1000 + iB) * 2 + 1] = tB1;
                smAcc += sl1(tB0 - e0) + sl1(tB1 - e1);
            }
        }
    }

    s_red[tid] = smAcc;
    __syncthreads();
#pragma unroll
    for (int s = 128; s > 0; s >>= 1) {
        if (tid < s) s_red[tid] += s_red[tid + s];
        __syncthreads();
    }
    if (tid == 0) g_off_part[b * 4 + blockIdx.x] = s_red[0];
}

// ---------------- K3: per-batch stats, policy, top-50 ----------------
__global__ void __launch_bounds__(512) finalize_kernel(const float* __restrict__ end,
                                                       float* __restrict__ out) {
    __shared__ float s_t[2000];
    __shared__ float s_p[2000];
    __shared__ float s_pd[1024];
    __shared__ u64 s_key[1024];
    __shared__ float s_w[32];
    __shared__ int   s_wi[16];
    __shared__ float s_bc[8];
    __shared__ int s_bi;

    int b = blockIdx.x, tid = threadIdx.x;
    int wid = tid >> 5, lane = tid & 31;

    for (int i = tid; i < 2000; i += 512) {
        s_t[i] = g_targets[b * 2000 + i];
        s_p[i] = g_pts[b * 2000 + i];
    }
    __syncthreads();

    // mean
    float a0 = 0.f, a1 = 0.f;
    for (int i = tid; i < 1000; i += 512) { a0 += s_t[2 * i]; a1 += s_t[2 * i + 1]; }
    a0 = wsum(a0); a1 = wsum(a1);
    if (lane == 0) { s_w[wid] = a0; s_w[16 + wid] = a1; }
    __syncthreads();
    if (tid < 32) {
        float v = s_w[tid];
        v += __shfl_xor_sync(0xffffffffu, v, 8);
        v += __shfl_xor_sync(0xffffffffu, v, 4);
        v += __shfl_xor_sync(0xffffffffu, v, 2);
        v += __shfl_xor_sync(0xffffffffu, v, 1);
        if ((tid & 15) == 0) s_bc[tid >> 4] = v * 0.001f;
    }
    __syncthreads();
    float m0 = s_bc[0], m1 = s_bc[1];

    // var (ddof=1)
    float q0 = 0.f, q1 = 0.f;
    for (int i = tid; i < 1000; i += 512) {
        float d0 = s_t[2 * i] - m0, d1 = s_t[2 * i + 1] - m1;
        q0 += d0 * d0; q1 += d1 * d1;
    }
    q0 = wsum(q0); q1 = wsum(q1);
    if (lane == 0) { s_w[wid] = q0; s_w[16 + wid] = q1; }
    __syncthreads();
    if (tid < 32) {
        float v = s_w[tid];
        v += __shfl_xor_sync(0xffffffffu, v, 8);
        v += __shfl_xor_sync(0xffffffffu, v, 4);
        v += __shfl_xor_sync(0xffffffffu, v, 2);
        v += __shfl_xor_sync(0xffffffffu, v, 1);
        if ((tid & 15) == 0) s_bc[2 + (tid >> 4)] = v / 999.0f;
    }
    __syncthreads();
    float v0 = s_bc[2], v1 = s_bc[3];

    // policy_dist
    float den0 = sqrtf(6.2831853071795864f * v0 + 1e-6f);
    float den1 = sqrtf(6.2831853071795864f * v1 + 1e-6f);
    for (int i = tid; i < 1024; i += 512) {
        float pd = -1.0f;
        if (i < 1000) {
            float dx = s_t[2 * i] - m0, dy = s_t[2 * i + 1] - m1;
            float pdx = expf(-0.5f * dx * dx / v0 + 1e-6f) / den0;
            float pdy = expf(-0.5f * dy * dy / v1 + 1e-6f) / den1;
            pd = pdx * pdy;
        }
        s_pd[i] = pd;
    }
    __syncthreads();

    // max(pd)
    float mx = -1.0f;
    for (int i = tid; i < 1000; i += 512) mx = fmaxf(mx, s_pd[i]);
#pragma unroll
    for (int o = 16; o; o >>= 1) mx = fmaxf(mx, __shfl_xor_sync(0xffffffffu, mx, o));
    if (lane == 0) s_w[wid] = mx;
    __syncthreads();
    if (tid < 32) {
        float v = (tid < 16) ? s_w[tid] : -3.4e38f;
        v = fmaxf(v, __shfl_xor_sync(0xffffffffu, v, 8));
        v = fmaxf(v, __shfl_xor_sync(0xffffffffu, v, 4));
        v = fmaxf(v, __shfl_xor_sync(0xffffffffu, v, 2));
        v = fmaxf(v, __shfl_xor_sync(0xffffffffu, v, 1));
        if (tid == 0) s_bc[4] = v;
    }
    __syncthreads();
    mx = s_bc[4];

    // sum exp(pd - mx)
    float se = 0.f;
    for (int i = tid; i < 1000; i += 512) se += expf(s_pd[i] - mx);
    se = wsum(se);
    if (lane == 0) s_w[wid] = se;
    __syncthreads();
    if (tid < 32) {
        float v = (tid < 16) ? s_w[tid] : 0.0f;
        v += __shfl_xor_sync(0xffffffffu, v, 8);
        v += __shfl_xor_sync(0xffffffffu, v, 4);
        v += __shfl_xor_sync(0xffffffffu, v, 2);
        v += __shfl_xor_sync(0xffffffffu, v, 1);
        if (tid == 0) s_bc[5] = v;
    }
    __syncthreads();
    float lse = mx + logf(s_bc[5]);

    // argmin distance to end (first-index tiebreak)
    float e0 = end[2 * b], e1 = end[2 * b + 1];
    float bd = 3.4e38f; int bi = 0x7fffffff;
    for (int i = tid; i < 1000; i += 512) {
        float dx = s_p[2 * i] - e0;
        float dy = s_p[2 * i + 1] - e1;
        float ds = sqrtf(dx * dx + dy * dy);
        if (ds < bd || (ds == bd && i < bi)) { bd = ds; bi = i; }
    }
#pragma unroll
    for (int o = 16; o; o >>= 1) {
        float od = __shfl_xor_sync(0xffffffffu, bd, o);
        int   oi = __shfl_xor_sync(0xffffffffu, bi, o);
        if (od < bd || (od == bd && oi < bi)) { bd = od; bi = oi; }
    }
    if (lane == 0) { s_w[wid] = bd; s_wi[wid] = bi; }
    __syncthreads();
    if (tid < 32) {
        float v  = (tid < 16) ? s_w[tid]  : 3.4e38f;
        int   vi = (tid < 16) ? s_wi[tid] : 0x7fffffff;
#pragma unroll
        for (int o = 8; o; o >>= 1) {
            float od = __shfl_xor_sync(0xffffffffu, v, o);
            int   oi = __shfl_xor_sync(0xffffffffu, vi, o);
            if (od < v || (od == v && oi < vi)) { v = od; vi = oi; }
        }
        if (tid == 0) s_bi = vi;
    }
    __syncthreads();
    float picked = s_pd[s_bi];

    // top-50 by pd desc, stable by index (bitonic)
    for (int i = tid; i < 1024; i += 512) {
        u32 pb = (i < 1000) ? __float_as_uint(s_pd[i]) : 0u;
        s_key[i] = ((u64)(0xFFFFFFFFu - pb) << 32) | (u32)i;
    }
    bool lastBig = true;
    for (int k = 2; k <= 1024; k <<= 1) {
        for (int j = k >> 1; j > 0; j >>= 1) {
            bool big = (j >= 64);
            if (big || lastBig) __syncthreads(); else __syncwarp();
            int i0 = ((tid & ~(j - 1)) << 1) | (tid & (j - 1));
            int i1 = i0 | j;
            bool up = ((i0 & k) == 0);
            u64 A = s_key[i0], B = s_key[i1];
            if ((A > B) == up) { s_key[i0] = B; s_key[i1] = A; }
            lastBig = big;
        }
    }
    __syncthreads();

    float es = 0.f;
    if (tid < 50) {
        int id = (int)(u32)(s_key[tid] & 0xffffffffull);
        float t0 = s_t[2 * id], t1 = s_t[2 * id + 1];
        out[2 + (b * 50 + tid) * 2]     = t0;
        out[2 + (b * 50 + tid) * 2 + 1] = t1;
        es = sl1(t0 - e0) + sl1(t1 - e1);
    }
    es = wsum(es);
    if (lane == 0) s_w[wid] = es;
    __syncthreads();
    if (tid == 0) {
        float tot = 0.f;
#pragma unroll
        for (int w = 0; w < 16; w++) tot += s_w[w];
        g_cls[b] = lse - picked;
        g_endsum[b] = tot;
    }
}

// ---------------- K4: final scalar reductions ----------------
__global__ void __launch_bounds__(512) reduce_kernel(float* __restrict__ out) {
    __shared__ float r[512];
    int tid = threadIdx.x;
    float offs = 0.f;
    for (int i = tid; i < 2048; i += 512) offs += g_off_part[i];
    float cls = g_cls[tid];
    float ends = g_endsum[tid];

    r[tid] = offs; __syncthreads();
    for (int s = 256; s > 0; s >>= 1) { if (tid < s) r[tid] += r[tid + s]; __syncthreads(); }
    float offT = r[0]; __syncthreads();
    r[tid] = cls; __syncthreads();
    for (int s = 256; s > 0; s >>= 1) { if (tid < s) r[tid] += r[tid + s]; __syncthreads(); }
    float clsT = r[0]; __syncthreads();
    r[tid] = ends; __syncthreads();
    for (int s = 256; s > 0; s >>= 1) { if (tid < s) r[tid] += r[tid + s]; __syncthreads(); }
    float endT = r[0];

    if (tid == 0) {
        out[0] = clsT / 512.0f;
        out[1] = offT / 1024000.0f + 3.0f * (endT / 51200.0f);
    }
}

extern "C" void kernel_launch(void* const* d_in, const int* in_sizes, int n_in,
                              void* d_out, int out_size) {
    const float* osm   = (const float*)d_in[0];
    const float* at    = (const float*)d_in[1];
    const float* vf    = (const float*)d_in[2];
    const float* end   = (const float*)d_in[3];
    const float* ox_w1 = (const float*)d_in[5];
    const float* ox_b1 = (const float*)d_in[6];
    const float* ox_g1 = (const float*)d_in[7];
    const float* ox_be1= (const float*)d_in[8];
    const float* ox_w2 = (const float*)d_in[9];
    const float* ox_b2 = (const float*)d_in[10];
    const float* tp_w1 = (const float*)d_in[11];
    const float* tp_b1 = (const float*)d_in[12];
    const float* tp_g1 = (const float*)d_in[13];
    const float* tp_be1= (const float*)d_in[14];
    const float* tp_w2 = (const float*)d_in[15];
    const float* tp_b2 = (const float*)d_in[16];
    const float* tp_g2 = (const float*)d_in[17];
    const float* tp_be2= (const float*)d_in[18];
    const float* tp_w3 = (const float*)d_in[19];
    const float* tp_b3 = (const float*)d_in[20];
    float* out = (float*)d_out;

    precompute_kernel<<<512, 256>>>(at, vf, ox_w1, ox_b1, tp_w1, tp_b1);
    select_kernel<<<512, 1024>>>(osm);
    dim3 g(4, 512);
    mlp_kernel<<<g, 256, MLP_DSMEM>>>(ox_w1, ox_g1, ox_be1, ox_w2, ox_b2,
                                      tp_w1, tp_g1, tp_be1, tp_w2, tp_b2,
                                      tp_g2, tp_be2, tp_w3, tp_b3, end);
    finalize_kernel<<<512, 512>>>(end, out);
    reduce_kernel<<<1, 512>>>(out);
}

// round 7
// speedup vs baseline: 1.1001x; 1.1001x over previous
#include <cuda_runtime.h>
#include <cuda_bf16.h>
#include <cstdint>

typedef unsigned long long u64;
typedef unsigned int u32;

// ---------------- scratch ----------------
__device__ float g_pre_ox[512 * 64];
__device__ float g_pre_tp[512 * 64];
__device__ float g_pts[512 * 1000 * 2];
__device__ float g_targets[512 * 1000 * 2];
__device__ float g_off_part[512 * 4];
__device__ float g_cls[512];
__device__ float g_endsum[512];

// ---------------- packed f32x2 helpers ----------------
__device__ __forceinline__ u64 F2(float a, float b) {
    u64 r; asm("mov.b64 %0,{%1,%2};" : "=l"(r) : "f"(a), "f"(b)); return r;
}
__device__ __forceinline__ void UNPK(u64 v, float& a, float& b) {
    asm("mov.b64 {%0,%1},%2;" : "=f"(a), "=f"(b) : "l"(v));
}
__device__ __forceinline__ u64 FMA2(u64 a, u64 b, u64 c) {
    u64 d; asm("fma.rn.f32x2 %0,%1,%2,%3;" : "=l"(d) : "l"(a), "l"(b), "l"(c)); return d;
}
__device__ __forceinline__ u64 ADD2(u64 a, u64 b) {
    u64 d; asm("add.rn.f32x2 %0,%1,%2;" : "=l"(d) : "l"(a), "l"(b)); return d;
}
__device__ __forceinline__ u64 MUL2(u64 a, u64 b) {
    u64 d; asm("mul.rn.f32x2 %0,%1,%2;" : "=l"(d) : "l"(a), "l"(b)); return d;
}
__device__ __forceinline__ u64 LD2(const float* p) {
    return *reinterpret_cast<const u64*>(p);
}
__device__ __forceinline__ u64 C2(float c) { return F2(c, c); }

__device__ __forceinline__ float sl1(float z) {
    float d = fabsf(z);
    return d < 1.0f ? 0.5f * d * d : d - 0.5f;
}

// Packed branchless exact-GELU (A&S 7.1.26 erfc; per-element bit-identical
// to the scalar version that passed R4/R5).
__device__ __forceinline__ u64 fast_gelu2(u64 z2) {
    u64 az = z2 & 0x7fffffff7fffffffull;
    u64 u2 = MUL2(az, C2(0.70710678118654752f));
    u64 dn = FMA2(u2, C2(0.3275911f), C2(1.0f));
    float d0, d1; UNPK(dn, d0, d1);
    float t0, t1;
    asm("rcp.approx.f32 %0, %1;" : "=f"(t0) : "f"(d0));
    asm("rcp.approx.f32 %0, %1;" : "=f"(t1) : "f"(d1));
    u64 t2 = F2(t0, t1);
    u64 gg = MUL2(MUL2(u2, u2), C2(-1.4426950408889634f));
    float g0, g1; UNPK(gg, g0, g1);
    float e0, e1;
    asm("ex2.approx.f32 %0, %1;" : "=f"(e0) : "f"(g0));
    asm("ex2.approx.f32 %0, %1;" : "=f"(e1) : "f"(g1));
    u64 p2 = FMA2(t2, C2(1.061405429f), C2(-1.453152027f));
    p2 = FMA2(p2, t2, C2(1.421413741f));
    p2 = FMA2(p2, t2, C2(-0.284496736f));
    p2 = FMA2(p2, t2, C2(0.254829592f));
    u64 q2 = MUL2(MUL2(p2, t2), F2(e0, e1));
    float z0, z1; UNPK(z2, z0, z1);
    u64 rl = F2(fmaxf(z0, 0.f), fmaxf(z1, 0.f));
    return FMA2(MUL2(az, C2(-0.5f)), q2, rl);
}

// tf32 round
__device__ __forceinline__ u32 tf32_rna(float x) {
    u32 r; asm("cvt.rna.tf32.f32 %0, %1;" : "=r"(r) : "f"(x)); return r;
}
// m16n8k8 tf32 MMA, D += A*B
__device__ __forceinline__ void mma8(float* c, const u32* a, u32 b0, u32 b1) {
    asm volatile(
        "mma.sync.aligned.m16n8k8.row.col.f32.tf32.tf32.f32 "
        "{%0,%1,%2,%3},{%4,%5,%6,%7},{%8,%9},{%0,%1,%2,%3};"
        : "+f"(c[0]), "+f"(c[1]), "+f"(c[2]), "+f"(c[3])
        : "r"(a[0]), "r"(a[1]), "r"(a[2]), "r"(a[3]), "r"(b0), "r"(b1));
}

__device__ __forceinline__ float qsum(float v) {
    v += __shfl_xor_sync(0xffffffffu, v, 1);
    v += __shfl_xor_sync(0xffffffffu, v, 2);
    return v;
}
__device__ __forceinline__ float wsum(float v) {
#pragma unroll
    for (int o = 16; o; o >>= 1) v += __shfl_xor_sync(0xffffffffu, v, o);
    return v;
}

// LN (eps 1e-5) + packed GELU on two fragment rows.
__device__ __forceinline__ void ln_gelu_frag(u64* hA, u64* hB,
                                             const float* gp, const float* bep, int tig) {
    u64 sa = hA[0], sb = hB[0];
#pragma unroll
    for (int kt = 1; kt < 8; kt++) { sa = ADD2(sa, hA[kt]); sb = ADD2(sb, hB[kt]); }
    float a0, a1, b0, b1; UNPK(sa, a0, a1); UNPK(sb, b0, b1);
    float mA = qsum(a0 + a1) * 0.015625f;
    float mB = qsum(b0 + b1) * 0.015625f;
    u64 mA2 = F2(-mA, -mA), mB2 = F2(-mB, -mB);
    u64 qa = F2(0.f, 0.f), qb = F2(0.f, 0.f);
#pragma unroll
    for (int kt = 0; kt < 8; kt++) {
        hA[kt] = ADD2(hA[kt], mA2); qa = FMA2(hA[kt], hA[kt], qa);
        hB[kt] = ADD2(hB[kt], mB2); qb = FMA2(hB[kt], hB[kt], qb);
    }
    UNPK(qa, a0, a1); UNPK(qb, b0, b1);
    float rA = rsqrtf(qsum(a0 + a1) * 0.015625f + 1e-5f);
    float rB = rsqrtf(qsum(b0 + b1) * 0.015625f + 1e-5f);
    u64 rA2 = F2(rA, rA), rB2 = F2(rB, rB);
#pragma unroll
    for (int kt = 0; kt < 8; kt++) {
        int o = 8 * kt + 2 * tig;
        u64 g2 = LD2(&gp[o]), be2 = LD2(&bep[o]);
        hA[kt] = fast_gelu2(FMA2(MUL2(hA[kt], rA2), g2, be2));
        hB[kt] = fast_gelu2(FMA2(MUL2(hB[kt], rB2), g2, be2));
    }
}

// ---------------- K0: per-batch precompute (4-way k-split) ----------------
__global__ void __launch_bounds__(256) precompute_kernel(
    const float* __restrict__ at, const float* __restrict__ vf,
    const float* __restrict__ ox_w1, const float* __restrict__ ox_b1,
    const float* __restrict__ tp_w1, const float* __restrict__ tp_b1) {
    __shared__ float s_vf[64], s_at[64];
    __shared__ float pa[4][64], pt[4][64];
    int b = blockIdx.x, tid = threadIdx.x;
    int c = tid & 63, kq = tid >> 6;
    if (tid < 64) { s_vf[tid] = vf[b * 64 + tid]; s_at[tid] = at[b * 64 + tid]; }
    __syncthreads();
    float a = 0.f, t = 0.f;
#pragma unroll
    for (int k = kq * 16; k < kq * 16 + 16; k++) {
        a += s_vf[k] * ox_w1[k * 64 + c] + s_at[k] * ox_w1[(64 + k) * 64 + c];
        t += s_vf[k] * tp_w1[k * 64 + c] + s_at[k] * tp_w1[(64 + k) * 64 + c];
    }
    pa[kq][c] = a; pt[kq][c] = t;
    __syncthreads();
    if (tid < 64) {
        g_pre_ox[b * 64 + tid] = pa[0][tid] + pa[1][tid] + pa[2][tid] + pa[3][tid] + ox_b1[tid];
        g_pre_tp[b * 64 + tid] = pt[0][tid] + pt[1][tid] + pt[2][tid] + pt[3][tid] + tp_b1[tid];
    }
}

// ---------------- K1: top-1000 selection (bitonic 2048) ----------------
__global__ void __launch_bounds__(1024) select_kernel(const float* __restrict__ osm) {
    __shared__ u64 s[2048];
    int b = blockIdx.x, t = threadIdx.x;
#pragma unroll
    for (int m = t; m < 2048; m += 1024) {
        u64 key;
        if (m < 2000) {
            float x = osm[(b * 2000 + m) * 4];
            float y = osm[(b * 2000 + m) * 4 + 1];
            float d2 = x * x + y * y;
            key = ((u64)__float_as_uint(d2) << 32) | (u32)m;
        } else key = ~0ull;
        s[m] = key;
    }
    bool lastBig = true;
    for (int k = 2; k <= 2048; k <<= 1) {
        for (int j = k >> 1; j > 0; j >>= 1) {
            bool big = (j >= 64);
            if (big || lastBig) __syncthreads(); else __syncwarp();
            int i0 = ((t & ~(j - 1)) << 1) | (t & (j - 1));
            int i1 = i0 | j;
            bool up = ((i0 & k) == 0);
            u64 A = s[i0], B = s[i1];
            if ((A > B) == up) { s[i0] = B; s[i1] = A; }
            lastBig = big;
        }
    }
    __syncthreads();
    if (t < 1000) {
        u32 m = (u32)(s[t] & 0xffffffffull);
        g_pts[(b * 1000 + t) * 2]     = osm[(b * 2000 + m) * 4];
        g_pts[(b * 1000 + t) * 2 + 1] = osm[(b * 2000 + m) * 4 + 1];
    }
}

// ---------------- K2: per-point MLP, fragment-native, tf32 3-term GEMM ----------------
#define WSTR 136
#define MLP_DSMEM (64 * WSTR * 4)

#define T_PRE_OX 0
#define T_OXX    1
#define T_OXY    2
#define T_OXG    3
#define T_OXBE   4
#define T_W2A    5
#define T_W2B    6
#define T_PRE_TP 7
#define T_TPX    8
#define T_TPY    9
#define T_G1     10
#define T_BE1    11

__global__ void __launch_bounds__(256, 2) mlp_kernel(
    const float* __restrict__ ox_w1, const float* __restrict__ ox_g1, const float* __restrict__ ox_be1,
    const float* __restrict__ ox_w2, const float* __restrict__ ox_b2,
    const float* __restrict__ tp_w1, const float* __restrict__ tp_g1, const float* __restrict__ tp_be1,
    const float* __restrict__ tp_w2, const float* __restrict__ tp_b2,
    const float* __restrict__ tp_g2, const float* __restrict__ tp_be2,
    const float* __restrict__ tp_w3, const float* __restrict__ tp_b3,
    const float* __restrict__ end) {
    extern __shared__ float w2i[];   // [64][WSTR], (hi,lo) tf32 interleaved per element
    __shared__ __align__(16) float P[12][64];
    __shared__ __align__(16) float s_b2[64], s_g2[64], s_be2[64], s_w3[128];
    __shared__ float s_red[256];

    int b = blockIdx.y;
    int tid = threadIdx.x;

    if (tid < 64) { s_b2[tid] = tp_b2[tid]; s_g2[tid] = tp_g2[tid]; s_be2[tid] = tp_be2[tid]; }
    if (tid < 128) s_w3[tid] = tp_w3[tid];
    if (tid < 32) {
        int c0 = (tid >> 2) * 8 + (tid & 3), c1 = c0 + 4;
        int o = 2 * tid;
        P[T_PRE_OX][o] = g_pre_ox[b * 64 + c0]; P[T_PRE_OX][o + 1] = g_pre_ox[b * 64 + c1];
        P[T_PRE_TP][o] = g_pre_tp[b * 64 + c0]; P[T_PRE_TP][o + 1] = g_pre_tp[b * 64 + c1];
        P[T_OXX][o] = ox_w1[128 * 64 + c0];     P[T_OXX][o + 1] = ox_w1[128 * 64 + c1];
        P[T_OXY][o] = ox_w1[129 * 64 + c0];     P[T_OXY][o + 1] = ox_w1[129 * 64 + c1];
        P[T_TPX][o] = tp_w1[128 * 64 + c0];     P[T_TPX][o + 1] = tp_w1[128 * 64 + c1];
        P[T_TPY][o] = tp_w1[129 * 64 + c0];     P[T_TPY][o + 1] = tp_w1[129 * 64 + c1];
        P[T_OXG][o] = ox_g1[c0];                P[T_OXG][o + 1] = ox_g1[c1];
        P[T_OXBE][o] = ox_be1[c0];              P[T_OXBE][o + 1] = ox_be1[c1];
        P[T_G1][o] = tp_g1[c0];                 P[T_G1][o + 1] = tp_g1[c1];
        P[T_BE1][o] = tp_be1[c0];               P[T_BE1][o + 1] = tp_be1[c1];
        P[T_W2A][o] = ox_w2[2 * c0];            P[T_W2A][o + 1] = ox_w2[2 * c1];
        P[T_W2B][o] = ox_w2[2 * c0 + 1];        P[T_W2B][o + 1] = ox_w2[2 * c1 + 1];
    }
    // W2 -> tf32 (hi,lo) interleaved
    for (int i = tid; i < 4096; i += 256) {
        float w = tp_w2[i];
        u32 hb = tf32_rna(w);
        float hif = __uint_as_float(hb);
        float lof = __uint_as_float(tf32_rna(w - hif));
        int k = i >> 6, n = i & 63;
        *reinterpret_cast<u64*>(&w2i[k * WSTR + 2 * n]) = F2(hif, lof);
    }
    __syncthreads();

    int wid = tid >> 5, lane = tid & 31;
    int gid = lane >> 2, tig = lane & 3;
    float ex = end[2 * b], ey = end[2 * b + 1];
    float b2o0 = ox_b2[0], b2o1 = ox_b2[1];
    float b3_0 = tp_b3[0], b3_1 = tp_b3[1];
    float smAcc = 0.f;

#pragma unroll 1
    for (int mt = 0; mt < 2; mt++) {
        int iA = blockIdx.x * 256 + wid * 32 + mt * 16 + gid;
        int iB = iA + 8;
        float xA = 0.f, yA = 0.f, xB = 0.f, yB = 0.f;
        if (iA < 1000) { float2 v = *reinterpret_cast<const float2*>(&g_pts[(b * 1000 + iA) * 2]); xA = v.x; yA = v.y; }
        if (iB < 1000) { float2 v = *reinterpret_cast<const float2*>(&g_pts[(b * 1000 + iB) * 2]); xB = v.x; yB = v.y; }

        u64 hA[8], hB[8];
        // layer1-ox
        {
            u64 xA2 = F2(xA, xA), yA2 = F2(yA, yA), xB2 = F2(xB, xB), yB2 = F2(yB, yB);
#pragma unroll
            for (int kt = 0; kt < 8; kt++) {
                int o = 8 * kt + 2 * tig;
                u64 pre = LD2(&P[T_PRE_OX][o]), wx = LD2(&P[T_OXX][o]), wy = LD2(&P[T_OXY][o]);
                hA[kt] = FMA2(yA2, wy, FMA2(xA2, wx, pre));
                hB[kt] = FMA2(yB2, wy, FMA2(xB2, wx, pre));
            }
        }
        ln_gelu_frag(hA, hB, &P[T_OXG][0], &P[T_OXBE][0], tig);

        // offset head
        float txA, tyA, txB, tyB;
        {
            u64 axA = F2(0.f, 0.f), ayA = axA, axB = axA, ayB = axA;
#pragma unroll
            for (int kt = 0; kt < 8; kt++) {
                int o = 8 * kt + 2 * tig;
                u64 wa = LD2(&P[T_W2A][o]), wb = LD2(&P[T_W2B][o]);
                axA = FMA2(hA[kt], wa, axA); ayA = FMA2(hA[kt], wb, ayA);
                axB = FMA2(hB[kt], wa, axB); ayB = FMA2(hB[kt], wb, ayB);
            }
            float p0, p1;
            UNPK(axA, p0, p1); txA = xA + qsum(p0 + p1) + b2o0;
            UNPK(ayA, p0, p1); tyA = yA + qsum(p0 + p1) + b2o1;
            UNPK(axB, p0, p1); txB = xB + qsum(p0 + p1) + b2o0;
            UNPK(ayB, p0, p1); tyB = yB + qsum(p0 + p1) + b2o1;
        }

        // layer1-tp
        {
            u64 xA2 = F2(txA, txA), yA2 = F2(tyA, tyA), xB2 = F2(txB, txB), yB2 = F2(tyB, tyB);
#pragma unroll
            for (int kt = 0; kt < 8; kt++) {
                int o = 8 * kt + 2 * tig;
                u64 pre = LD2(&P[T_PRE_TP][o]), wx = LD2(&P[T_TPX][o]), wy = LD2(&P[T_TPY][o]);
                hA[kt] = FMA2(yA2, wy, FMA2(xA2, wx, pre));
                hB[kt] = FMA2(yB2, wy, FMA2(xB2, wx, pre));
            }
        }
        ln_gelu_frag(hA, hB, &P[T_G1][0], &P[T_BE1][0], tig);

        // GEMM: 16x64 @ 64x64, tf32 3-term
        float cst[8][4];
#pragma unroll
        for (int nt = 0; nt < 8; nt++)
#pragma unroll
            for (int qq = 0; qq < 4; qq++) cst[nt][qq] = 0.f;

#pragma unroll
        for (int kt = 0; kt < 8; kt++) {
            float a0, a2; UNPK(hA[kt], a0, a2);
            float a1, a3; UNPK(hB[kt], a1, a3);
            u32 ah[4], al[4];
            ah[0] = tf32_rna(a0); al[0] = tf32_rna(a0 - __uint_as_float(ah[0]));
            ah[1] = tf32_rna(a1); al[1] = tf32_rna(a1 - __uint_as_float(ah[1]));
            ah[2] = tf32_rna(a2); al[2] = tf32_rna(a2 - __uint_as_float(ah[2]));
            ah[3] = tf32_rna(a3); al[3] = tf32_rna(a3 - __uint_as_float(ah[3]));
            int kc = kt * 8 + tig;
            const float* r0p = &w2i[kc * WSTR];
            const float* r1p = &w2i[(kc + 4) * WSTR];
#pragma unroll
            for (int nt = 0; nt < 8; nt++) {
                int nc2 = 2 * (nt * 8 + gid);
                u64 w0 = LD2(r0p + nc2);
                u64 w1 = LD2(r1p + nc2);
                float fh, fl;
                u32 bh0, bl0, bh1, bl1;
                UNPK(w0, fh, fl); bh0 = __float_as_uint(fh); bl0 = __float_as_uint(fl);
                UNPK(w1, fh, fl); bh1 = __float_as_uint(fh); bl1 = __float_as_uint(fl);
                mma8(cst[nt], ah, bh0, bh1);
                mma8(cst[nt], ah, bl0, bl1);
                mma8(cst[nt], al, bh0, bh1);
            }
        }

        // epilogue: packed +bias, LN, GELU, 64->2 (x/y packed in one acc)
        u64 cA[8], cB[8];
#pragma unroll
        for (int nt = 0; nt < 8; nt++) {
            int col0 = nt * 8 + 2 * tig;
            u64 b2p = LD2(&s_b2[col0]);
            cA[nt] = ADD2(F2(cst[nt][0], cst[nt][1]), b2p);
            cB[nt] = ADD2(F2(cst[nt][2], cst[nt][3]), b2p);
        }
        u64 sa = cA[0], sb = cB[0];
#pragma unroll
        for (int nt = 1; nt < 8; nt++) { sa = ADD2(sa, cA[nt]); sb = ADD2(sb, cB[nt]); }
        float s0, s1;
        UNPK(sa, s0, s1); float mA = qsum(s0 + s1) * 0.015625f;
        UNPK(sb, s0, s1); float mB = qsum(s0 + s1) * 0.015625f;
        u64 mA2 = F2(-mA, -mA), mB2 = F2(-mB, -mB);
        u64 qa = F2(0.f, 0.f), qb = F2(0.f, 0.f);
#pragma unroll
        for (int nt = 0; nt < 8; nt++) {
            cA[nt] = ADD2(cA[nt], mA2); qa = FMA2(cA[nt], cA[nt], qa);
            cB[nt] = ADD2(cB[nt], mB2); qb = FMA2(cB[nt], cB[nt], qb);
        }
        UNPK(qa, s0, s1); float rA = rsqrtf(qsum(s0 + s1) * 0.015625f + 1e-5f);
        UNPK(qb, s0, s1); float rB = rsqrtf(qsum(s0 + s1) * 0.015625f + 1e-5f);
        u64 rA2 = F2(rA, rA), rB2 = F2(rB, rB);

        u64 accA = F2(0.f, 0.f), accB = F2(0.f, 0.f);
#pragma unroll
        for (int nt = 0; nt < 8; nt++) {
            int col0 = nt * 8 + 2 * tig;
            u64 g2 = LD2(&s_g2[col0]), be2 = LD2(&s_be2[col0]);
            u64 zA = fast_gelu2(FMA2(MUL2(cA[nt], rA2), g2, be2));
            u64 zB = fast_gelu2(FMA2(MUL2(cB[nt], rB2), g2, be2));
            float z0, z1;
            UNPK(zA, z0, z1);
            accA = FMA2(F2(z0, z0), LD2(&s_w3[2 * col0]), accA);
            accA = FMA2(F2(z1, z1), LD2(&s_w3[2 * col0 + 2]), accA);
            UNPK(zB, z0, z1);
            accB = FMA2(F2(z0, z0), LD2(&s_w3[2 * col0]), accB);
            accB = FMA2(F2(z1, z1), LD2(&s_w3[2 * col0 + 2]), accB);
        }
        float px, py;
        UNPK(accA, px, py); float pA0 = qsum(px), pA1 = qsum(py);
        UNPK(accB, px, py); float pB0 = qsum(px), pB1 = qsum(py);

        if (tig == 0) {
            float tA0 = pA0 + b3_0, tA1 = pA1 + b3_1;
            float tB0 = pB0 + b3_0, tB1 = pB1 + b3_1;
            if (iA < 1000) {
                g_targets[(b * 1000 + iA) * 2]     = tA0;
                g_targets[(b * 1000 + iA) * 2 + 1] = tA1;
                smAcc += sl1(tA0 - ex) + sl1(tA1 - ey);
            }
            if (iB < 1000) {
                g_targets[(b * 1000 + iB) * 2]     = tB0;
                g_targets[(b * 1000 + iB) * 2 + 1] = tB1;
                smAcc += sl1(tB0 - ex) + sl1(tB1 - ey);
            }
        }
    }

    s_red[tid] = smAcc;
    __syncthreads();
#pragma unroll
    for (int s = 128; s > 0; s >>= 1) {
        if (tid < s) s_red[tid] += s_red[tid + s];
        __syncthreads();
    }
    if (tid == 0) g_off_part[b * 4 + blockIdx.x] = s_red[0];
}

// ---------------- K3: per-batch stats, policy, top-50 (warp bitonic top-k) ----------------
__global__ void __launch_bounds__(512) finalize_kernel(const float* __restrict__ end,
                                                       float* __restrict__ out) {
    __shared__ float s_t[2000];
    __shared__ float s_p[2000];
    __shared__ float s_pd[1024];
    __shared__ u64 s_key[1024];
    __shared__ float s_w[32];
    __shared__ int   s_wi[16];
    __shared__ float s_bc[8];
    __shared__ int s_bi;

    int b = blockIdx.x, tid = threadIdx.x;
    int wid = tid >> 5, lane = tid & 31;

    for (int i = tid; i < 2000; i += 512) {
        s_t[i] = g_targets[b * 2000 + i];
        s_p[i] = g_pts[b * 2000 + i];
    }
    __syncthreads();

    // mean
    float a0 = 0.f, a1 = 0.f;
    for (int i = tid; i < 1000; i += 512) { a0 += s_t[2 * i]; a1 += s_t[2 * i + 1]; }
    a0 = wsum(a0); a1 = wsum(a1);
    if (lane == 0) { s_w[wid] = a0; s_w[16 + wid] = a1; }
    __syncthreads();
    if (tid < 32) {
        float v = s_w[tid];
        v += __shfl_xor_sync(0xffffffffu, v, 8);
        v += __shfl_xor_sync(0xffffffffu, v, 4);
        v += __shfl_xor_sync(0xffffffffu, v, 2);
        v += __shfl_xor_sync(0xffffffffu, v, 1);
        if ((tid & 15) == 0) s_bc[tid >> 4] = v * 0.001f;
    }
    __syncthreads();
    float m0 = s_bc[0], m1 = s_bc[1];

    // var (ddof=1)
    float q0 = 0.f, q1 = 0.f;
    for (int i = tid; i < 1000; i += 512) {
        float d0 = s_t[2 * i] - m0, d1 = s_t[2 * i + 1] - m1;
        q0 += d0 * d0; q1 += d1 * d1;
    }
    q0 = wsum(q0); q1 = wsum(q1);
    if (lane == 0) { s_w[wid] = q0; s_w[16 + wid] = q1; }
    __syncthreads();
    if (tid < 32) {
        float v = s_w[tid];
        v += __shfl_xor_sync(0xffffffffu, v, 8);
        v += __shfl_xor_sync(0xffffffffu, v, 4);
        v += __shfl_xor_sync(0xffffffffu, v, 2);
        v += __shfl_xor_sync(0xffffffffu, v, 1);
        if ((tid & 15) == 0) s_bc[2 + (tid >> 4)] = v / 999.0f;
    }
    __syncthreads();
    float v0 = s_bc[2], v1 = s_bc[3];

    // policy_dist
    float den0 = sqrtf(6.2831853071795864f * v0 + 1e-6f);
    float den1 = sqrtf(6.2831853071795864f * v1 + 1e-6f);
    for (int i = tid; i < 1024; i += 512) {
        float pd = -1.0f;
        if (i < 1000) {
            float dx = s_t[2 * i] - m0, dy = s_t[2 * i + 1] - m1;
            float pdx = expf(-0.5f * dx * dx / v0 + 1e-6f) / den0;
            float pdy = expf(-0.5f * dy * dy / v1 + 1e-6f) / den1;
            pd = pdx * pdy;
        }
        s_pd[i] = pd;
    }
    __syncthreads();

    // max(pd)
    float mx = -1.0f;
    for (int i = tid; i < 1000; i += 512) mx = fmaxf(mx, s_pd[i]);
#pragma unroll
    for (int o = 16; o; o >>= 1) mx = fmaxf(mx, __shfl_xor_sync(0xffffffffu, mx, o));
    if (lane == 0) s_w[wid] = mx;
    __syncthreads();
    if (tid < 32) {
        float v = (tid < 16) ? s_w[tid] : -3.4e38f;
        v = fmaxf(v, __shfl_xor_sync(0xffffffffu, v, 8));
        v = fmaxf(v, __shfl_xor_sync(0xffffffffu, v, 4));
        v = fmaxf(v, __shfl_xor_sync(0xffffffffu, v, 2));
        v = fmaxf(v, __shfl_xor_sync(0xffffffffu, v, 1));
        if (tid == 0) s_bc[4] = v;
    }
    __syncthreads();
    mx = s_bc[4];

    // sum exp(pd - mx)
    float se = 0.f;
    for (int i = tid; i < 1000; i += 512) se += expf(s_pd[i] - mx);
    se = wsum(se);
    if (lane == 0) s_w[wid] = se;
    __syncthreads();
    if (tid < 32) {
        float v = (tid < 16) ? s_w[tid] : 0.0f;
        v += __shfl_xor_sync(0xffffffffu, v, 8);
        v += __shfl_xor_sync(0xffffffffu, v, 4);
        v += __shfl_xor_sync(0xffffffffu, v, 2);
        v += __shfl_xor_sync(0xffffffffu, v, 1);
        if (tid == 0) s_bc[5] = v;
    }
    __syncthreads();
    float lse = mx + logf(s_bc[5]);

    // argmin distance to end (first-index tiebreak)
    float ex = end[2 * b], ey = end[2 * b + 1];
    float bd = 3.4e38f; int bi = 0x7fffffff;
    for (int i = tid; i < 1000; i += 512) {
        float dx = s_p[2 * i] - ex;
        float dy = s_p[2 * i + 1] - ey;
        float ds = sqrtf(dx * dx + dy * dy);
        if (ds < bd || (ds == bd && i < bi)) { bd = ds; bi = i; }
    }
#pragma unroll
    for (int o = 16; o; o >>= 1) {
        float od = __shfl_xor_sync(0xffffffffu, bd, o);
        int   oi = __shfl_xor_sync(0xffffffffu, bi, o);
        if (od < bd || (od == bd && oi < bi)) { bd = od; bi = oi; }
    }
    if (lane == 0) { s_w[wid] = bd; s_wi[wid] = bi; }
    __syncthreads();
    if (tid < 32) {
        float v  = (tid < 16) ? s_w[tid]  : 3.4e38f;
        int   vi = (tid < 16) ? s_wi[tid] : 0x7fffffff;
#pragma unroll
        for (int o = 8; o; o >>= 1) {
            float od = __shfl_xor_sync(0xffffffffu, v, o);
            int   oi = __shfl_xor_sync(0xffffffffu, vi, o);
            if (od < v || (od == v && oi < vi)) { v = od; vi = oi; }
        }
        if (tid == 0) s_bi = vi;
    }
    __syncthreads();
    float picked = s_pd[s_bi];

    // ---- top-50: warp-register bitonic top-k ----
    // key = (pd_bits << 32) | ~idx  -> descending sort == (pd desc, idx asc)
    u64 k0, k1;
    {
        int i0 = wid * 64 + lane, i1 = i0 + 32;
        k0 = (i0 < 1000) ? ((((u64)__float_as_uint(s_pd[i0])) << 32) | (u32)(~i0)) : 0ull;
        k1 = (i1 < 1000) ? ((((u64)__float_as_uint(s_pd[i1])) << 32) | (u32)(~i1)) : 0ull;
    }
    // warp-local descending sort of 64 (pos0 = lane, pos1 = lane+32)
#pragma unroll
    for (int k = 2; k <= 64; k <<= 1) {
#pragma unroll
        for (int j = k >> 1; j > 0; j >>= 1) {
            if (j == 32) {
                u64 mxk = k0 > k1 ? k0 : k1;
                u64 mnk = k0 > k1 ? k1 : k0;
                k0 = mxk; k1 = mnk;
            } else {
                u64 o0 = __shfl_xor_sync(0xffffffffu, k0, j);
                u64 o1 = __shfl_xor_sync(0xffffffffu, k1, j);
                bool low = (lane & j) == 0;
                bool d0 = (lane & k) == 0;
                bool d1 = (((lane + 32) & k) == 0);
                bool t0 = (low == d0), t1 = (low == d1);
                k0 = t0 ? (k0 > o0 ? k0 : o0) : (k0 < o0 ? k0 : o0);
                k1 = t1 ? (k1 > o1 ? k1 : o1) : (k1 < o1 ? k1 : o1);
            }
        }
    }
    // tournament max-merge: 16 -> 1 chunks, keeping top-64 each stage
    s_key[wid * 64 + lane] = k0;
    s_key[wid * 64 + 32 + lane] = k1;
    __syncthreads();
#pragma unroll
    for (int act = 8; act >= 1; act >>= 1) {
        if (wid < act) {
            u64 a0 = s_key[(2 * wid) * 64 + lane];
            u64 a1 = s_key[(2 * wid) * 64 + 32 + lane];
            u64 b0 = s_key[(2 * wid + 1) * 64 + 63 - lane];
            u64 b1 = s_key[(2 * wid + 1) * 64 + 31 - lane];
            k0 = a0 > b0 ? a0 : b0;
            k1 = a1 > b1 ? a1 : b1;
            // bitonic merge (descending, 64)
            { u64 mxk = k0 > k1 ? k0 : k1, mnk = k0 > k1 ? k1 : k0; k0 = mxk; k1 = mnk; }
#pragma unroll
            for (int j = 16; j > 0; j >>= 1) {
                u64 o0 = __shfl_xor_sync(0xffffffffu, k0, j);
                u64 o1 = __shfl_xor_sync(0xffffffffu, k1, j);
                bool tm = (lane & j) == 0;
                k0 = tm ? (k0 > o0 ? k0 : o0) : (k0 < o0 ? k0 : o0);
                k1 = tm ? (k1 > o1 ? k1 : o1) : (k1 < o1 ? k1 : o1);
            }
        }
        __syncthreads();
        if (act > 1 && wid < act) {
            s_key[wid * 64 + lane] = k0;
            s_key[wid * 64 + 32 + lane] = k1;
        }
        __syncthreads();
    }

    // warp 0 holds the global top-64 descending; emit top-50 + smooth-L1 partial
    if (wid == 0) {
        float es = 0.f;
        u32 id = ~(u32)k0;
        float t0 = s_t[2 * id], t1 = s_t[2 * id + 1];
        out[2 + (b * 50 + lane) * 2]     = t0;
        out[2 + (b * 50 + lane) * 2 + 1] = t1;
        es = sl1(t0 - ex) + sl1(t1 - ey);
        if (lane < 18) {
            u32 id2 = ~(u32)k1;
            float u0 = s_t[2 * id2], u1 = s_t[2 * id2 + 1];
            int pos = 32 + lane;
            out[2 + (b * 50 + pos) * 2]     = u0;
            out[2 + (b * 50 + pos) * 2 + 1] = u1;
            es += sl1(u0 - ex) + sl1(u1 - ey);
        }
        es = wsum(es);
        if (lane == 0) {
            g_cls[b] = lse - picked;
            g_endsum[b] = es;
        }
    }
}

// ---------------- K4: final scalar reductions ----------------
__global__ void __launch_bounds__(512) reduce_kernel(float* __restrict__ out) {
    __shared__ float r[512];
    int tid = threadIdx.x;
    float offs = 0.f;
    for (int i = tid; i < 2048; i += 512) offs += g_off_part[i];
    float cls = g_cls[tid];
    float ends = g_endsum[tid];

    r[tid] = offs; __syncthreads();
    for (int s = 256; s > 0; s >>= 1) { if (tid < s) r[tid] += r[tid + s]; __syncthreads(); }
    float offT = r[0]; __syncthreads();
    r[tid] = cls; __syncthreads();
    for (int s = 256; s > 0; s >>= 1) { if (tid < s) r[tid] += r[tid + s]; __syncthreads(); }
    float clsT = r[0]; __syncthreads();
    r[tid] = ends; __syncthreads();
    for (int s = 256; s > 0; s >>= 1) { if (tid < s) r[tid] += r[tid + s]; __syncthreads(); }
    float endT = r[0];

    if (tid == 0) {
        out[0] = clsT / 512.0f;
        out[1] = offT / 1024000.0f + 3.0f * (endT / 51200.0f);
    }
}

extern "C" void kernel_launch(void* const* d_in, const int* in_sizes, int n_in,
                              void* d_out, int out_size) {
    const float* osm   = (const float*)d_in[0];
    const float* at    = (const float*)d_in[1];
    const float* vf    = (const float*)d_in[2];
    const float* end   = (const float*)d_in[3];
    const float* ox_w1 = (const float*)d_in[5];
    const float* ox_b1 = (const float*)d_in[6];
    const float* ox_g1 = (const float*)d_in[7];
    const float* ox_be1= (const float*)d_in[8];
    const float* ox_w2 = (const float*)d_in[9];
    const float* ox_b2 = (const float*)d_in[10];
    const float* tp_w1 = (const float*)d_in[11];
    const float* tp_b1 = (const float*)d_in[12];
    const float* tp_g1 = (const float*)d_in[13];
    const float* tp_be1= (const float*)d_in[14];
    const float* tp_w2 = (const float*)d_in[15];
    const float* tp_b2 = (const float*)d_in[16];
    const float* tp_g2 = (const float*)d_in[17];
    const float* tp_be2= (const float*)d_in[18];
    const float* tp_w3 = (const float*)d_in[19];
    const float* tp_b3 = (const float*)d_in[20];
    float* out = (float*)d_out;

    precompute_kernel<<<512, 256>>>(at, vf, ox_w1, ox_b1, tp_w1, tp_b1);
    select_kernel<<<512, 1024>>>(osm);
    dim3 g(4, 512);
    mlp_kernel<<<g, 256, MLP_DSMEM>>>(ox_w1, ox_g1, ox_be1, ox_w2, ox_b2,
                                      tp_w1, tp_g1, tp_be1, tp_w2, tp_b2,
                                      tp_g2, tp_be2, tp_w3, tp_b3, end);
    finalize_kernel<<<512, 512>>>(end, out);
    reduce_kernel<<<1, 512>>>(out);
}

// round 8
// speedup vs baseline: 1.2737x; 1.1579x over previous
#include <cuda_runtime.h>
#include <cuda_fp16.h>
#include <cuda_bf16.h>
#include <cstdint>

typedef unsigned long long u64;
typedef unsigned int u32;

// ---------------- scratch ----------------
__device__ float g_pre_ox[512 * 64];
__device__ float g_pre_tp[512 * 64];
__device__ float g_pts[512 * 1000 * 2];
__device__ float g_targets[512 * 1000 * 2];
__device__ float g_off_part[512 * 4];
__device__ float g_cls[512];
__device__ float g_endsum[512];

// ---------------- packed f32x2 helpers ----------------
__device__ __forceinline__ u64 F2(float a, float b) {
    u64 r; asm("mov.b64 %0,{%1,%2};" : "=l"(r) : "f"(a), "f"(b)); return r;
}
__device__ __forceinline__ void UNPK(u64 v, float& a, float& b) {
    asm("mov.b64 {%0,%1},%2;" : "=f"(a), "=f"(b) : "l"(v));
}
__device__ __forceinline__ u64 FMA2(u64 a, u64 b, u64 c) {
    u64 d; asm("fma.rn.f32x2 %0,%1,%2,%3;" : "=l"(d) : "l"(a), "l"(b), "l"(c)); return d;
}
__device__ __forceinline__ u64 ADD2(u64 a, u64 b) {
    u64 d; asm("add.rn.f32x2 %0,%1,%2;" : "=l"(d) : "l"(a), "l"(b)); return d;
}
__device__ __forceinline__ u64 MUL2(u64 a, u64 b) {
    u64 d; asm("mul.rn.f32x2 %0,%1,%2;" : "=l"(d) : "l"(a), "l"(b)); return d;
}
__device__ __forceinline__ u64 LD2(const float* p) {
    return *reinterpret_cast<const u64*>(p);
}
__device__ __forceinline__ u64 C2(float c) { return F2(c, c); }

__device__ __forceinline__ float sl1(float z) {
    float d = fabsf(z);
    return d < 1.0f ? 0.5f * d * d : d - 0.5f;
}

// Packed branchless exact-GELU (A&S 7.1.26 erfc; per-element identical
// to the scalar version validated in R4/R5/R7).
__device__ __forceinline__ u64 fast_gelu2(u64 z2) {
    u64 az = z2 & 0x7fffffff7fffffffull;
    u64 u2 = MUL2(az, C2(0.70710678118654752f));
    u64 dn = FMA2(u2, C2(0.3275911f), C2(1.0f));
    float d0, d1; UNPK(dn, d0, d1);
    float t0, t1;
    asm("rcp.approx.f32 %0, %1;" : "=f"(t0) : "f"(d0));
    asm("rcp.approx.f32 %0, %1;" : "=f"(t1) : "f"(d1));
    u64 t2 = F2(t0, t1);
    u64 gg = MUL2(MUL2(u2, u2), C2(-1.4426950408889634f));
    float g0, g1; UNPK(gg, g0, g1);
    float e0, e1;
    asm("ex2.approx.f32 %0, %1;" : "=f"(e0) : "f"(g0));
    asm("ex2.approx.f32 %0, %1;" : "=f"(e1) : "f"(g1));
    u64 p2 = FMA2(t2, C2(1.061405429f), C2(-1.453152027f));
    p2 = FMA2(p2, t2, C2(1.421413741f));
    p2 = FMA2(p2, t2, C2(-0.284496736f));
    p2 = FMA2(p2, t2, C2(0.254829592f));
    u64 q2 = MUL2(MUL2(p2, t2), F2(e0, e1));
    float z0, z1; UNPK(z2, z0, z1);
    u64 rl = F2(fmaxf(z0, 0.f), fmaxf(z1, 0.f));
    return FMA2(MUL2(az, C2(-0.5f)), q2, rl);
}

// split f32 pair -> f16x2 hi + f16x2 residual lo (lo16 of reg = first elem)
__device__ __forceinline__ void hsplit(u64 xy, u32& h, u32& l) {
    float x, y; UNPK(xy, x, y);
    __half2 hh = __floats2half2_rn(x, y);
    h = *reinterpret_cast<u32*>(&hh);
    float2 bk = __half22float2(hh);
    __half2 hl = __floats2half2_rn(x - bk.x, y - bk.y);
    l = *reinterpret_cast<u32*>(&hl);
}

// m16n8k16 fp16 MMA, f32 accum, D += A*B
__device__ __forceinline__ void mma16f(float* c, const u32* a, u32 b0, u32 b1) {
    asm volatile(
        "mma.sync.aligned.m16n8k16.row.col.f32.f16.f16.f32 "
        "{%0,%1,%2,%3},{%4,%5,%6,%7},{%8,%9},{%0,%1,%2,%3};"
        : "+f"(c[0]), "+f"(c[1]), "+f"(c[2]), "+f"(c[3])
        : "r"(a[0]), "r"(a[1]), "r"(a[2]), "r"(a[3]), "r"(b0), "r"(b1));
}

__device__ __forceinline__ float qsum(float v) {
    v += __shfl_xor_sync(0xffffffffu, v, 1);
    v += __shfl_xor_sync(0xffffffffu, v, 2);
    return v;
}
__device__ __forceinline__ float wsum(float v) {
#pragma unroll
    for (int o = 16; o; o >>= 1) v += __shfl_xor_sync(0xffffffffu, v, o);
    return v;
}

// LN (eps 1e-5) + packed GELU on two fragment rows; lane covers cols 8j+2tig,+1.
__device__ __forceinline__ void ln_gelu_frag(u64* hA, u64* hB,
                                             const float* gp, const float* bep, int tig) {
    u64 sa = hA[0], sb = hB[0];
#pragma unroll
    for (int j = 1; j < 8; j++) { sa = ADD2(sa, hA[j]); sb = ADD2(sb, hB[j]); }
    float a0, a1, b0, b1; UNPK(sa, a0, a1); UNPK(sb, b0, b1);
    float mA = qsum(a0 + a1) * 0.015625f;
    float mB = qsum(b0 + b1) * 0.015625f;
    u64 mA2 = F2(-mA, -mA), mB2 = F2(-mB, -mB);
    u64 qa = F2(0.f, 0.f), qb = F2(0.f, 0.f);
#pragma unroll
    for (int j = 0; j < 8; j++) {
        hA[j] = ADD2(hA[j], mA2); qa = FMA2(hA[j], hA[j], qa);
        hB[j] = ADD2(hB[j], mB2); qb = FMA2(hB[j], hB[j], qb);
    }
    UNPK(qa, a0, a1); UNPK(qb, b0, b1);
    float rA = rsqrtf(qsum(a0 + a1) * 0.015625f + 1e-5f);
    float rB = rsqrtf(qsum(b0 + b1) * 0.015625f + 1e-5f);
    u64 rA2 = F2(rA, rA), rB2 = F2(rB, rB);
#pragma unroll
    for (int j = 0; j < 8; j++) {
        int o = 8 * j + 2 * tig;
        u64 g2 = LD2(&gp[o]), be2 = LD2(&bep[o]);
        hA[j] = fast_gelu2(FMA2(MUL2(hA[j], rA2), g2, be2));
        hB[j] = fast_gelu2(FMA2(MUL2(hB[j], rB2), g2, be2));
    }
}

// ---------------- K-: profiling pad (shifts ncu capture slot onto mlp) ----------------
__global__ void prof_pad_kernel() {}

// ---------------- K0: per-batch precompute (4-way k-split) ----------------
__global__ void __launch_bounds__(256) precompute_kernel(
    const float* __restrict__ at, const float* __restrict__ vf,
    const float* __restrict__ ox_w1, const float* __restrict__ ox_b1,
    const float* __restrict__ tp_w1, const float* __restrict__ tp_b1) {
    __shared__ float s_vf[64], s_at[64];
    __shared__ float pa[4][64], pt[4][64];
    int b = blockIdx.x, tid = threadIdx.x;
    int c = tid & 63, kq = tid >> 6;
    if (tid < 64) { s_vf[tid] = vf[b * 64 + tid]; s_at[tid] = at[b * 64 + tid]; }
    __syncthreads();
    float a = 0.f, t = 0.f;
#pragma unroll
    for (int k = kq * 16; k < kq * 16 + 16; k++) {
        a += s_vf[k] * ox_w1[k * 64 + c] + s_at[k] * ox_w1[(64 + k) * 64 + c];
        t += s_vf[k] * tp_w1[k * 64 + c] + s_at[k] * tp_w1[(64 + k) * 64 + c];
    }
    pa[kq][c] = a; pt[kq][c] = t;
    __syncthreads();
    if (tid < 64) {
        g_pre_ox[b * 64 + tid] = pa[0][tid] + pa[1][tid] + pa[2][tid] + pa[3][tid] + ox_b1[tid];
        g_pre_tp[b * 64 + tid] = pt[0][tid] + pt[1][tid] + pt[2][tid] + pt[3][tid] + tp_b1[tid];
    }
}

// ---------------- K1: top-1000 selection (bitonic 2048) ----------------
__global__ void __launch_bounds__(1024) select_kernel(const float* __restrict__ osm) {
    __shared__ u64 s[2048];
    int b = blockIdx.x, t = threadIdx.x;
#pragma unroll
    for (int m = t; m < 2048; m += 1024) {
        u64 key;
        if (m < 2000) {
            float x = osm[(b * 2000 + m) * 4];
            float y = osm[(b * 2000 + m) * 4 + 1];
            float d2 = x * x + y * y;
            key = ((u64)__float_as_uint(d2) << 32) | (u32)m;
        } else key = ~0ull;
        s[m] = key;
    }
    bool lastBig = true;
    for (int k = 2; k <= 2048; k <<= 1) {
        for (int j = k >> 1; j > 0; j >>= 1) {
            bool big = (j >= 64);
            if (big || lastBig) __syncthreads(); else __syncwarp();
            int i0 = ((t & ~(j - 1)) << 1) | (t & (j - 1));
            int i1 = i0 | j;
            bool up = ((i0 & k) == 0);
            u64 A = s[i0], B = s[i1];
            if ((A > B) == up) { s[i0] = B; s[i1] = A; }
            lastBig = big;
        }
    }
    __syncthreads();
    if (t < 1000) {
        u32 m = (u32)(s[t] & 0xffffffffull);
        g_pts[(b * 1000 + t) * 2]     = osm[(b * 2000 + m) * 4];
        g_pts[(b * 1000 + t) * 2 + 1] = osm[(b * 2000 + m) * 4 + 1];
    }
}

// ---------------- K2: per-point MLP, fragment-native, fp16 3-term k16 GEMM ----------------
#define W4STR 66
#define MLP_DSMEM (16 * W4STR * 16)

#define T_PRE_OX 0
#define T_OXX    1
#define T_OXY    2
#define T_OXG    3
#define T_OXBE   4
#define T_W2A    5
#define T_W2B    6
#define T_PRE_TP 7
#define T_TPX    8
#define T_TPY    9
#define T_G1     10
#define T_BE1    11

__global__ void __launch_bounds__(256, 2) mlp_kernel(
    const float* __restrict__ ox_w1, const float* __restrict__ ox_g1, const float* __restrict__ ox_be1,
    const float* __restrict__ ox_w2, const float* __restrict__ ox_b2,
    const float* __restrict__ tp_w1, const float* __restrict__ tp_g1, const float* __restrict__ tp_be1,
    const float* __restrict__ tp_w2, const float* __restrict__ tp_b2,
    const float* __restrict__ tp_g2, const float* __restrict__ tp_be2,
    const float* __restrict__ tp_w3, const float* __restrict__ tp_b3,
    const float* __restrict__ end) {
    // w4[row= kt*4 + (kp&3)][n] = { hi(kp0), hi(kp0+4), lo(kp0), lo(kp0+4) }
    // where kp indexes k-pairs (k = 2kp, 2kp+1), kp0 = 8kt + tig.
    extern __shared__ uint4 w4[];
    __shared__ __align__(16) float P[12][64];
    __shared__ __align__(16) float s_b2[64], s_g2[64], s_be2[64], s_w3[128];
    __shared__ float s_red[256];

    int b = blockIdx.y;
    int tid = threadIdx.x;

    if (tid < 64) {
        P[T_PRE_OX][tid] = g_pre_ox[b * 64 + tid];
        P[T_PRE_TP][tid] = g_pre_tp[b * 64 + tid];
        P[T_OXX][tid] = ox_w1[128 * 64 + tid];
        P[T_OXY][tid] = ox_w1[129 * 64 + tid];
        P[T_TPX][tid] = tp_w1[128 * 64 + tid];
        P[T_TPY][tid] = tp_w1[129 * 64 + tid];
        P[T_OXG][tid] = ox_g1[tid];
        P[T_OXBE][tid] = ox_be1[tid];
        P[T_G1][tid] = tp_g1[tid];
        P[T_BE1][tid] = tp_be1[tid];
        P[T_W2A][tid] = ox_w2[2 * tid];
        P[T_W2B][tid] = ox_w2[2 * tid + 1];
        s_b2[tid] = tp_b2[tid]; s_g2[tid] = tp_g2[tid]; s_be2[tid] = tp_be2[tid];
    }
    if (tid < 128) s_w3[tid] = tp_w3[tid];
    // W2 -> fp16 hi/lo fragments in b-frag layout
    for (int i = tid; i < 2048; i += 256) {
        int kp = i >> 6, n = i & 63;
        float w0 = tp_w2[(2 * kp) * 64 + n];
        float w1 = tp_w2[(2 * kp + 1) * 64 + n];
        __half2 hh = __floats2half2_rn(w0, w1);
        u32 hi = *reinterpret_cast<u32*>(&hh);
        float2 bk = __half22float2(hh);
        __half2 hl = __floats2half2_rn(w0 - bk.x, w1 - bk.y);
        u32 lo = *reinterpret_cast<u32*>(&hl);
        int kt = kp >> 3, rem = kp & 7;
        int row = kt * 4 + (rem & 3);
        int second = rem >> 2;           // 0: kp0 slot, 1: kp0+4 slot
        u32* base = reinterpret_cast<u32*>(&w4[row * W4STR + n]);
        base[second]     = hi;
        base[2 + second] = lo;
    }
    __syncthreads();

    int wid = tid >> 5, lane = tid & 31;
    int gid = lane >> 2, tig = lane & 3;
    float ex = end[2 * b], ey = end[2 * b + 1];
    float b2o0 = ox_b2[0], b2o1 = ox_b2[1];
    float b3_0 = tp_b3[0], b3_1 = tp_b3[1];
    float smAcc = 0.f;

#pragma unroll 1
    for (int mt = 0; mt < 2; mt++) {
        int iA = blockIdx.x * 256 + wid * 32 + mt * 16 + gid;
        int iB = iA + 8;
        float xA = 0.f, yA = 0.f, xB = 0.f, yB = 0.f;
        if (iA < 1000) { float2 v = *reinterpret_cast<const float2*>(&g_pts[(b * 1000 + iA) * 2]); xA = v.x; yA = v.y; }
        if (iB < 1000) { float2 v = *reinterpret_cast<const float2*>(&g_pts[(b * 1000 + iB) * 2]); xB = v.x; yB = v.y; }

        u64 hA[8], hB[8];   // hA[j] = row gid, cols 8j+2tig,+1 ; hB = row gid+8
        // layer1-ox
        {
            u64 xA2 = F2(xA, xA), yA2 = F2(yA, yA), xB2 = F2(xB, xB), yB2 = F2(yB, yB);
#pragma unroll
            for (int j = 0; j < 8; j++) {
                int o = 8 * j + 2 * tig;
                u64 pre = LD2(&P[T_PRE_OX][o]), wx = LD2(&P[T_OXX][o]), wy = LD2(&P[T_OXY][o]);
                hA[j] = FMA2(yA2, wy, FMA2(xA2, wx, pre));
                hB[j] = FMA2(yB2, wy, FMA2(xB2, wx, pre));
            }
        }
        ln_gelu_frag(hA, hB, &P[T_OXG][0], &P[T_OXBE][0], tig);

        // offset head
        float txA, tyA, txB, tyB;
        {
            u64 axA = F2(0.f, 0.f), ayA = axA, axB = axA, ayB = axA;
#pragma unroll
            for (int j = 0; j < 8; j++) {
                int o = 8 * j + 2 * tig;
                u64 wa = LD2(&P[T_W2A][o]), wb = LD2(&P[T_W2B][o]);
                axA = FMA2(hA[j], wa, axA); ayA = FMA2(hA[j], wb, ayA);
                axB = FMA2(hB[j], wa, axB); ayB = FMA2(hB[j], wb, ayB);
            }
            float p0, p1;
            UNPK(axA, p0, p1); txA = xA + qsum(p0 + p1) + b2o0;
            UNPK(ayA, p0, p1); tyA = yA + qsum(p0 + p1) + b2o1;
            UNPK(axB, p0, p1); txB = xB + qsum(p0 + p1) + b2o0;
            UNPK(ayB, p0, p1); tyB = yB + qsum(p0 + p1) + b2o1;
        }

        // layer1-tp
        {
            u64 xA2 = F2(txA, txA), yA2 = F2(tyA, tyA), xB2 = F2(txB, txB), yB2 = F2(tyB, tyB);
#pragma unroll
            for (int j = 0; j < 8; j++) {
                int o = 8 * j + 2 * tig;
                u64 pre = LD2(&P[T_PRE_TP][o]), wx = LD2(&P[T_TPX][o]), wy = LD2(&P[T_TPY][o]);
                hA[j] = FMA2(yA2, wy, FMA2(xA2, wx, pre));
                hB[j] = FMA2(yB2, wy, FMA2(xB2, wx, pre));
            }
        }
        ln_gelu_frag(hA, hB, &P[T_G1][0], &P[T_BE1][0], tig);

        // GEMM: 16x64 @ 64x64, fp16 3-term (Ah·Bh + Al·Bh + Ah·Bl), k16 MMA
        float cst[8][4];
#pragma unroll
        for (int nt = 0; nt < 8; nt++)
#pragma unroll
            for (int qq = 0; qq < 4; qq++) cst[nt][qq] = 0.f;

#pragma unroll
        for (int kt = 0; kt < 4; kt++) {
            u32 ah[4], al[4];
            hsplit(hA[2 * kt],     ah[0], al[0]);   // row g,   cols 16kt+2tig,+1
            hsplit(hB[2 * kt],     ah[1], al[1]);   // row g+8
            hsplit(hA[2 * kt + 1], ah[2], al[2]);   // row g,   cols +8
            hsplit(hB[2 * kt + 1], ah[3], al[3]);   // row g+8
            const uint4* rp = &w4[(kt * 4 + tig) * W4STR];
#pragma unroll
            for (int nt = 0; nt < 8; nt++) {
                uint4 w = rp[8 * nt + gid];
                mma16f(cst[nt], ah, w.x, w.y);
                mma16f(cst[nt], al, w.x, w.y);
                mma16f(cst[nt], ah, w.z, w.w);
            }
        }

        // epilogue: packed +bias, LN, GELU, 64->2
        u64 cA[8], cB[8];
#pragma unroll
        for (int nt = 0; nt < 8; nt++) {
            int col0 = nt * 8 + 2 * tig;
            u64 b2p = LD2(&s_b2[col0]);
            cA[nt] = ADD2(F2(cst[nt][0], cst[nt][1]), b2p);
            cB[nt] = ADD2(F2(cst[nt][2], cst[nt][3]), b2p);
        }
        u64 sa = cA[0], sb = cB[0];
#pragma unroll
        for (int nt = 1; nt < 8; nt++) { sa = ADD2(sa, cA[nt]); sb = ADD2(sb, cB[nt]); }
        float s0, s1;
        UNPK(sa, s0, s1); float mA = qsum(s0 + s1) * 0.015625f;
        UNPK(sb, s0, s1); float mB = qsum(s0 + s1) * 0.015625f;
        u64 mA2 = F2(-mA, -mA), mB2 = F2(-mB, -mB);
        u64 qa = F2(0.f, 0.f), qb = F2(0.f, 0.f);
#pragma unroll
        for (int nt = 0; nt < 8; nt++) {
            cA[nt] = ADD2(cA[nt], mA2); qa = FMA2(cA[nt], cA[nt], qa);
            cB[nt] = ADD2(cB[nt], mB2); qb = FMA2(cB[nt], cB[nt], qb);
        }
        UNPK(qa, s0, s1); float rA = rsqrtf(qsum(s0 + s1) * 0.015625f + 1e-5f);
        UNPK(qb, s0, s1); float rB = rsqrtf(qsum(s0 + s1) * 0.015625f + 1e-5f);
        u64 rA2 = F2(rA, rA), rB2 = F2(rB, rB);

        u64 accA = F2(0.f, 0.f), accB = F2(0.f, 0.f);
#pragma unroll
        for (int nt = 0; nt < 8; nt++) {
            int col0 = nt * 8 + 2 * tig;
            u64 g2 = LD2(&s_g2[col0]), be2 = LD2(&s_be2[col0]);
            u64 zA = fast_gelu2(FMA2(MUL2(cA[nt], rA2), g2, be2));
            u64 zB = fast_gelu2(FMA2(MUL2(cB[nt], rB2), g2, be2));
            float z0, z1;
            UNPK(zA, z0, z1);
            accA = FMA2(F2(z0, z0), LD2(&s_w3[2 * col0]), accA);
            accA = FMA2(F2(z1, z1), LD2(&s_w3[2 * col0 + 2]), accA);
            UNPK(zB, z0, z1);
            accB = FMA2(F2(z0, z0), LD2(&s_w3[2 * col0]), accB);
            accB = FMA2(F2(z1, z1), LD2(&s_w3[2 * col0 + 2]), accB);
        }
        float px, py;
        UNPK(accA, px, py); float pA0 = qsum(px), pA1 = qsum(py);
        UNPK(accB, px, py); float pB0 = qsum(px), pB1 = qsum(py);

        if (tig == 0) {
            float tA0 = pA0 + b3_0, tA1 = pA1 + b3_1;
            float tB0 = pB0 + b3_0, tB1 = pB1 + b3_1;
            if (iA < 1000) {
                g_targets[(b * 1000 + iA) * 2]     = tA0;
                g_targets[(b * 1000 + iA) * 2 + 1] = tA1;
                smAcc += sl1(tA0 - ex) + sl1(tA1 - ey);
            }
            if (iB < 1000) {
                g_targets[(b * 1000 + iB) * 2]     = tB0;
                g_targets[(b * 1000 + iB) * 2 + 1] = tB1;
                smAcc += sl1(tB0 - ex) + sl1(tB1 - ey);
            }
        }
    }

    s_red[tid] = smAcc;
    __syncthreads();
#pragma unroll
    for (int s = 128; s > 0; s >>= 1) {
        if (tid < s) s_red[tid] += s_red[tid + s];
        __syncthreads();
    }
    if (tid == 0) g_off_part[b * 4 + blockIdx.x] = s_red[0];
}

// ---------------- K3: per-batch stats, policy, top-50 (warp bitonic top-k) ----------------
__global__ void __launch_bounds__(512) finalize_kernel(const float* __restrict__ end,
                                                       float* __restrict__ out) {
    __shared__ float s_t[2000];
    __shared__ float s_p[2000];
    __shared__ float s_pd[1024];
    __shared__ u64 s_key[1024];
    __shared__ float s_w[32];
    __shared__ int   s_wi[16];
    __shared__ float s_bc[8];
    __shared__ int s_bi;

    int b = blockIdx.x, tid = threadIdx.x;
    int wid = tid >> 5, lane = tid & 31;

    for (int i = tid; i < 2000; i += 512) {
        s_t[i] = g_targets[b * 2000 + i];
        s_p[i] = g_pts[b * 2000 + i];
    }
    __syncthreads();

    // mean
    float a0 = 0.f, a1 = 0.f;
    for (int i = tid; i < 1000; i += 512) { a0 += s_t[2 * i]; a1 += s_t[2 * i + 1]; }
    a0 = wsum(a0); a1 = wsum(a1);
    if (lane == 0) { s_w[wid] = a0; s_w[16 + wid] = a1; }
    __syncthreads();
    if (tid < 32) {
        float v = s_w[tid];
        v += __shfl_xor_sync(0xffffffffu, v, 8);
        v += __shfl_xor_sync(0xffffffffu, v, 4);
        v += __shfl_xor_sync(0xffffffffu, v, 2);
        v += __shfl_xor_sync(0xffffffffu, v, 1);
        if ((tid & 15) == 0) s_bc[tid >> 4] = v * 0.001f;
    }
    __syncthreads();
    float m0 = s_bc[0], m1 = s_bc[1];

    // var (ddof=1)
    float q0 = 0.f, q1 = 0.f;
    for (int i = tid; i < 1000; i += 512) {
        float d0 = s_t[2 * i] - m0, d1 = s_t[2 * i + 1] - m1;
        q0 += d0 * d0; q1 += d1 * d1;
    }
    q0 = wsum(q0); q1 = wsum(q1);
    if (lane == 0) { s_w[wid] = q0; s_w[16 + wid] = q1; }
    __syncthreads();
    if (tid < 32) {
        float v = s_w[tid];
        v += __shfl_xor_sync(0xffffffffu, v, 8);
        v += __shfl_xor_sync(0xffffffffu, v, 4);
        v += __shfl_xor_sync(0xffffffffu, v, 2);
        v += __shfl_xor_sync(0xffffffffu, v, 1);
        if ((tid & 15) == 0) s_bc[2 + (tid >> 4)] = v / 999.0f;
    }
    __syncthreads();
    float v0 = s_bc[2], v1 = s_bc[3];

    // policy_dist
    float den0 = sqrtf(6.2831853071795864f * v0 + 1e-6f);
    float den1 = sqrtf(6.2831853071795864f * v1 + 1e-6f);
    for (int i = tid; i < 1024; i += 512) {
        float pd = -1.0f;
        if (i < 1000) {
            float dx = s_t[2 * i] - m0, dy = s_t[2 * i + 1] - m1;
            float pdx = expf(-0.5f * dx * dx / v0 + 1e-6f) / den0;
            float pdy = expf(-0.5f * dy * dy / v1 + 1e-6f) / den1;
            pd = pdx * pdy;
        }
        s_pd[i] = pd;
    }
    __syncthreads();

    // max(pd)
    float mx = -1.0f;
    for (int i = tid; i < 1000; i += 512) mx = fmaxf(mx, s_pd[i]);
#pragma unroll
    for (int o = 16; o; o >>= 1) mx = fmaxf(mx, __shfl_xor_sync(0xffffffffu, mx, o));
    if (lane == 0) s_w[wid] = mx;
    __syncthreads();
    if (tid < 32) {
        float v = (tid < 16) ? s_w[tid] : -3.4e38f;
        v = fmaxf(v, __shfl_xor_sync(0xffffffffu, v, 8));
        v = fmaxf(v, __shfl_xor_sync(0xffffffffu, v, 4));
        v = fmaxf(v, __shfl_xor_sync(0xffffffffu, v, 2));
        v = fmaxf(v, __shfl_xor_sync(0xffffffffu, v, 1));
        if (tid == 0) s_bc[4] = v;
    }
    __syncthreads();
    mx = s_bc[4];

    // sum exp(pd - mx)
    float se = 0.f;
    for (int i = tid; i < 1000; i += 512) se += expf(s_pd[i] - mx);
    se = wsum(se);
    if (lane == 0) s_w[wid] = se;
    __syncthreads();
    if (tid < 32) {
        float v = (tid < 16) ? s_w[tid] : 0.0f;
        v += __shfl_xor_sync(0xffffffffu, v, 8);
        v += __shfl_xor_sync(0xffffffffu, v, 4);
        v += __shfl_xor_sync(0xffffffffu, v, 2);
        v += __shfl_xor_sync(0xffffffffu, v, 1);
        if (tid == 0) s_bc[5] = v;
    }
    __syncthreads();
    float lse = mx + logf(s_bc[5]);

    // argmin distance to end (first-index tiebreak)
    float ex = end[2 * b], ey = end[2 * b + 1];
    float bd = 3.4e38f; int bi = 0x7fffffff;
    for (int i = tid; i < 1000; i += 512) {
        float dx = s_p[2 * i] - ex;
        float dy = s_p[2 * i + 1] - ey;
        float ds = sqrtf(dx * dx + dy * dy);
        if (ds < bd || (ds == bd && i < bi)) { bd = ds; bi = i; }
    }
#pragma unroll
    for (int o = 16; o; o >>= 1) {
        float od = __shfl_xor_sync(0xffffffffu, bd, o);
        int   oi = __shfl_xor_sync(0xffffffffu, bi, o);
        if (od < bd || (od == bd && oi < bi)) { bd = od; bi = oi; }
    }
    if (lane == 0) { s_w[wid] = bd; s_wi[wid] = bi; }
    __syncthreads();
    if (tid < 32) {
        float v  = (tid < 16) ? s_w[tid]  : 3.4e38f;
        int   vi = (tid < 16) ? s_wi[tid] : 0x7fffffff;
#pragma unroll
        for (int o = 8; o; o >>= 1) {
            float od = __shfl_xor_sync(0xffffffffu, v, o);
            int   oi = __shfl_xor_sync(0xffffffffu, vi, o);
            if (od < v || (od == v && oi < vi)) { v = od; vi = oi; }
        }
        if (tid == 0) s_bi = vi;
    }
    __syncthreads();
    float picked = s_pd[s_bi];

    // ---- top-50: warp-register bitonic top-k ----
    u64 k0, k1;
    {
        int i0 = wid * 64 + lane, i1 = i0 + 32;
        k0 = (i0 < 1000) ? ((((u64)__float_as_uint(s_pd[i0])) << 32) | (u32)(~i0)) : 0ull;
        k1 = (i1 < 1000) ? ((((u64)__float_as_uint(s_pd[i1])) << 32) | (u32)(~i1)) : 0ull;
    }
#pragma unroll
    for (int k = 2; k <= 64; k <<= 1) {
#pragma unroll
        for (int j = k >> 1; j > 0; j >>= 1) {
            if (j == 32) {
                u64 mxk = k0 > k1 ? k0 : k1;
                u64 mnk = k0 > k1 ? k1 : k0;
                k0 = mxk; k1 = mnk;
            } else {
                u64 o0 = __shfl_xor_sync(0xffffffffu, k0, j);
                u64 o1 = __shfl_xor_sync(0xffffffffu, k1, j);
                bool low = (lane & j) == 0;
                bool d0 = (lane & k) == 0;
                bool d1 = (((lane + 32) & k) == 0);
                bool t0 = (low == d0), t1 = (low == d1);
                k0 = t0 ? (k0 > o0 ? k0 : o0) : (k0 < o0 ? k0 : o0);
                k1 = t1 ? (k1 > o1 ? k1 : o1) : (k1 < o1 ? k1 : o1);
            }
        }
    }
    s_key[wid * 64 + lane] = k0;
    s_key[wid * 64 + 32 + lane] = k1;
    __syncthreads();
#pragma unroll
    for (int act = 8; act >= 1; act >>= 1) {
        if (wid < act) {
            u64 a0k = s_key[(2 * wid) * 64 + lane];
            u64 a1k = s_key[(2 * wid) * 64 + 32 + lane];
            u64 b0k = s_key[(2 * wid + 1) * 64 + 63 - lane];
            u64 b1k = s_key[(2 * wid + 1) * 64 + 31 - lane];
            k0 = a0k > b0k ? a0k : b0k;
            k1 = a1k > b1k ? a1k : b1k;
            { u64 mxk = k0 > k1 ? k0 : k1, mnk = k0 > k1 ? k1 : k0; k0 = mxk; k1 = mnk; }
#pragma unroll
            for (int j = 16; j > 0; j >>= 1) {
                u64 o0 = __shfl_xor_sync(0xffffffffu, k0, j);
                u64 o1 = __shfl_xor_sync(0xffffffffu, k1, j);
                bool tm = (lane & j) == 0;
                k0 = tm ? (k0 > o0 ? k0 : o0) : (k0 < o0 ? k0 : o0);
                k1 = tm ? (k1 > o1 ? k1 : o1) : (k1 < o1 ? k1 : o1);
            }
        }
        __syncthreads();
        if (act > 1 && wid < act) {
            s_key[wid * 64 + lane] = k0;
            s_key[wid * 64 + 32 + lane] = k1;
        }
        __syncthreads();
    }

    if (wid == 0) {
        float es = 0.f;
        u32 id = ~(u32)k0;
        float t0 = s_t[2 * id], t1 = s_t[2 * id + 1];
        out[2 + (b * 50 + lane) * 2]     = t0;
        out[2 + (b * 50 + lane) * 2 + 1] = t1;
        es = sl1(t0 - ex) + sl1(t1 - ey);
        if (lane < 18) {
            u32 id2 = ~(u32)k1;
            float u0 = s_t[2 * id2], u1 = s_t[2 * id2 + 1];
            int pos = 32 + lane;
            out[2 + (b * 50 + pos) * 2]     = u0;
            out[2 + (b * 50 + pos) * 2 + 1] = u1;
            es += sl1(u0 - ex) + sl1(u1 - ey);
        }
        es = wsum(es);
        if (lane == 0) {
            g_cls[b] = lse - picked;
            g_endsum[b] = es;
        }
    }
}

// ---------------- K4: final scalar reductions ----------------
__global__ void __launch_bounds__(512) reduce_kernel(float* __restrict__ out) {
    __shared__ float r[512];
    int tid = threadIdx.x;
    float offs = 0.f;
    for (int i = tid; i < 2048; i += 512) offs += g_off_part[i];
    float cls = g_cls[tid];
    float ends = g_endsum[tid];

    r[tid] = offs; __syncthreads();
    for (int s = 256; s > 0; s >>= 1) { if (tid < s) r[tid] += r[tid + s]; __syncthreads(); }
    float offT = r[0]; __syncthreads();
    r[tid] = cls; __syncthreads();
    for (int s = 256; s > 0; s >>= 1) { if (tid < s) r[tid] += r[tid + s]; __syncthreads(); }
    float clsT = r[0]; __syncthreads();
    r[tid] = ends; __syncthreads();
    for (int s = 256; s > 0; s >>= 1) { if (tid < s) r[tid] += r[tid + s]; __syncthreads(); }
    float endT = r[0];

    if (tid == 0) {
        out[0] = clsT / 512.0f;
        out[1] = offT / 1024000.0f + 3.0f * (endT / 51200.0f);
    }
}

extern "C" void kernel_launch(void* const* d_in, const int* in_sizes, int n_in,
                              void* d_out, int out_size) {
    const float* osm   = (const float*)d_in[0];
    const float* at    = (const float*)d_in[1];
    const float* vf    = (const float*)d_in[2];
    const float* end   = (const float*)d_in[3];
    const float* ox_w1 = (const float*)d_in[5];
    const float* ox_b1 = (const float*)d_in[6];
    const float* ox_g1 = (const float*)d_in[7];
    const float* ox_be1= (const float*)d_in[8];
    const float* ox_w2 = (const float*)d_in[9];
    const float* ox_b2 = (const float*)d_in[10];
    const float* tp_w1 = (const float*)d_in[11];
    const float* tp_b1 = (const float*)d_in[12];
    const float* tp_g1 = (const float*)d_in[13];
    const float* tp_be1= (const float*)d_in[14];
    const float* tp_w2 = (const float*)d_in[15];
    const float* tp_b2 = (const float*)d_in[16];
    const float* tp_g2 = (const float*)d_in[17];
    const float* tp_be2= (const float*)d_in[18];
    const float* tp_w3 = (const float*)d_in[19];
    const float* tp_b3 = (const float*)d_in[20];
    float* out = (float*)d_out;

    prof_pad_kernel<<<1, 32>>>();   // shifts ncu capture slot onto mlp_kernel
    precompute_kernel<<<512, 256>>>(at, vf, ox_w1, ox_b1, tp_w1, tp_b1);
    select_kernel<<<512, 1024>>>(osm);
    dim3 g(4, 512);
    mlp_kernel<<<g, 256, MLP_DSMEM>>>(ox_w1, ox_g1, ox_be1, ox_w2, ox_b2,
                                      tp_w1, tp_g1, tp_be1, tp_w2, tp_b2,
                                      tp_g2, tp_be2, tp_w3, tp_b3, end);
    finalize_kernel<<<512, 512>>>(end, out);
    reduce_kernel<<<1, 512>>>(out);
}

// round 9
// speedup vs baseline: 1.3016x; 1.0219x over previous
#include <cuda_runtime.h>
#include <cuda_fp16.h>
#include <cuda_bf16.h>
#include <cstdint>

typedef unsigned long long u64;
typedef unsigned int u32;

// ---------------- scratch ----------------
__device__ float g_pre_ox[512 * 64];
__device__ float g_pre_tp[512 * 64];
__device__ float g_pts[512 * 1000 * 2];
__device__ float g_targets[512 * 1000 * 2];
__device__ float g_off_part[512 * 4];
__device__ float g_cls[512];
__device__ float g_endsum[512];

// ---------------- packed f32x2 helpers ----------------
__device__ __forceinline__ u64 F2(float a, float b) {
    u64 r; asm("mov.b64 %0,{%1,%2};" : "=l"(r) : "f"(a), "f"(b)); return r;
}
__device__ __forceinline__ void UNPK(u64 v, float& a, float& b) {
    asm("mov.b64 {%0,%1},%2;" : "=f"(a), "=f"(b) : "l"(v));
}
__device__ __forceinline__ u64 FMA2(u64 a, u64 b, u64 c) {
    u64 d; asm("fma.rn.f32x2 %0,%1,%2,%3;" : "=l"(d) : "l"(a), "l"(b), "l"(c)); return d;
}
__device__ __forceinline__ u64 ADD2(u64 a, u64 b) {
    u64 d; asm("add.rn.f32x2 %0,%1,%2;" : "=l"(d) : "l"(a), "l"(b)); return d;
}
__device__ __forceinline__ u64 MUL2(u64 a, u64 b) {
    u64 d; asm("mul.rn.f32x2 %0,%1,%2;" : "=l"(d) : "l"(a), "l"(b)); return d;
}
__device__ __forceinline__ u64 LD2(const float* p) {
    return *reinterpret_cast<const u64*>(p);
}
__device__ __forceinline__ u64 C2(float c) { return F2(c, c); }

__device__ __forceinline__ float sl1(float z) {
    float d = fabsf(z);
    return d < 1.0f ? 0.5f * d * d : d - 0.5f;
}

// Packed branchless exact-GELU (A&S 7.1.26 erfc). -0.5 folded into the
// polynomial coefficients (q2 is negative-half-erfc) -> one fewer MUL2.
__device__ __forceinline__ u64 fast_gelu2(u64 z2) {
    u64 az = z2 & 0x7fffffff7fffffffull;
    u64 u2 = MUL2(az, C2(0.70710678118654752f));
    u64 dn = FMA2(u2, C2(0.3275911f), C2(1.0f));
    float d0, d1; UNPK(dn, d0, d1);
    float t0, t1;
    asm("rcp.approx.f32 %0, %1;" : "=f"(t0) : "f"(d0));
    asm("rcp.approx.f32 %0, %1;" : "=f"(t1) : "f"(d1));
    u64 t2 = F2(t0, t1);
    u64 gg = MUL2(MUL2(u2, u2), C2(-1.4426950408889634f));
    float g0, g1; UNPK(gg, g0, g1);
    float e0, e1;
    asm("ex2.approx.f32 %0, %1;" : "=f"(e0) : "f"(g0));
    asm("ex2.approx.f32 %0, %1;" : "=f"(e1) : "f"(g1));
    u64 p2 = FMA2(t2, C2(-0.5307027145f), C2(0.7265760135f));
    p2 = FMA2(p2, t2, C2(-0.7107068705f));
    p2 = FMA2(p2, t2, C2(0.142248368f));
    p2 = FMA2(p2, t2, C2(-0.127414796f));
    u64 q2 = MUL2(MUL2(p2, t2), F2(e0, e1));
    float z0, z1; UNPK(z2, z0, z1);
    u64 rl = F2(fmaxf(z0, 0.f), fmaxf(z1, 0.f));
    return FMA2(az, q2, rl);
}

// split f32 pair -> f16x2 hi + f16x2 residual lo
__device__ __forceinline__ void hsplit(u64 xy, u32& h, u32& l) {
    float x, y; UNPK(xy, x, y);
    __half2 hh = __floats2half2_rn(x, y);
    h = *reinterpret_cast<u32*>(&hh);
    float2 bk = __half22float2(hh);
    __half2 hl = __floats2half2_rn(x - bk.x, y - bk.y);
    l = *reinterpret_cast<u32*>(&hl);
}

// m16n8k16 fp16 MMA, f32 accum, D += A*B
__device__ __forceinline__ void mma16f(float* c, const u32* a, u32 b0, u32 b1) {
    asm volatile(
        "mma.sync.aligned.m16n8k16.row.col.f32.f16.f16.f32 "
        "{%0,%1,%2,%3},{%4,%5,%6,%7},{%8,%9},{%0,%1,%2,%3};"
        : "+f"(c[0]), "+f"(c[1]), "+f"(c[2]), "+f"(c[3])
        : "r"(a[0]), "r"(a[1]), "r"(a[2]), "r"(a[3]), "r"(b0), "r"(b1));
}

__device__ __forceinline__ float qsum(float v) {
    v += __shfl_xor_sync(0xffffffffu, v, 1);
    v += __shfl_xor_sync(0xffffffffu, v, 2);
    return v;
}
__device__ __forceinline__ float wsum(float v) {
#pragma unroll
    for (int o = 16; o; o >>= 1) v += __shfl_xor_sync(0xffffffffu, v, o);
    return v;
}

// LN (eps 1e-5) + packed GELU on two fragment rows, means supplied (linearized).
__device__ __forceinline__ void ln_gelu_frag_m(u64* hA, u64* hB, float mA, float mB,
                                               const float* gp, const float* bep, int tig) {
    u64 mA2 = F2(-mA, -mA), mB2 = F2(-mB, -mB);
    u64 qa = F2(0.f, 0.f), qb = F2(0.f, 0.f);
#pragma unroll
    for (int j = 0; j < 8; j++) {
        hA[j] = ADD2(hA[j], mA2); qa = FMA2(hA[j], hA[j], qa);
        hB[j] = ADD2(hB[j], mB2); qb = FMA2(hB[j], hB[j], qb);
    }
    float a0, a1, b0, b1;
    UNPK(qa, a0, a1); UNPK(qb, b0, b1);
    float rA = rsqrtf(qsum(a0 + a1) * 0.015625f + 1e-5f);
    float rB = rsqrtf(qsum(b0 + b1) * 0.015625f + 1e-5f);
    u64 rA2 = F2(rA, rA), rB2 = F2(rB, rB);
#pragma unroll
    for (int j = 0; j < 8; j++) {
        int o = 8 * j + 2 * tig;
        u64 g2 = LD2(&gp[o]), be2 = LD2(&bep[o]);
        hA[j] = fast_gelu2(FMA2(MUL2(hA[j], rA2), g2, be2));
        hB[j] = fast_gelu2(FMA2(MUL2(hB[j], rB2), g2, be2));
    }
}

// ---------------- K-: profiling pad (keeps ncu capture slot on mlp) ----------------
__global__ void prof_pad_kernel() {}

// ---------------- K0: per-batch precompute (4-way k-split) ----------------
__global__ void __launch_bounds__(256) precompute_kernel(
    const float* __restrict__ at, const float* __restrict__ vf,
    const float* __restrict__ ox_w1, const float* __restrict__ ox_b1,
    const float* __restrict__ tp_w1, const float* __restrict__ tp_b1) {
    __shared__ float s_vf[64], s_at[64];
    __shared__ float pa[4][64], pt[4][64];
    int b = blockIdx.x, tid = threadIdx.x;
    int c = tid & 63, kq = tid >> 6;
    if (tid < 64) { s_vf[tid] = vf[b * 64 + tid]; s_at[tid] = at[b * 64 + tid]; }
    __syncthreads();
    float a = 0.f, t = 0.f;
#pragma unroll
    for (int k = kq * 16; k < kq * 16 + 16; k++) {
        a += s_vf[k] * ox_w1[k * 64 + c] + s_at[k] * ox_w1[(64 + k) * 64 + c];
        t += s_vf[k] * tp_w1[k * 64 + c] + s_at[k] * tp_w1[(64 + k) * 64 + c];
    }
    pa[kq][c] = a; pt[kq][c] = t;
    __syncthreads();
    if (tid < 64) {
        g_pre_ox[b * 64 + tid] = pa[0][tid] + pa[1][tid] + pa[2][tid] + pa[3][tid] + ox_b1[tid];
        g_pre_tp[b * 64 + tid] = pt[0][tid] + pt[1][tid] + pt[2][tid] + pt[3][tid] + tp_b1[tid];
    }
}

// ---------------- K1: top-1000 selection (bitonic 2048) ----------------
__global__ void __launch_bounds__(1024) select_kernel(const float* __restrict__ osm) {
    __shared__ u64 s[2048];
    int b = blockIdx.x, t = threadIdx.x;
#pragma unroll
    for (int m = t; m < 2048; m += 1024) {
        u64 key;
        if (m < 2000) {
            float x = osm[(b * 2000 + m) * 4];
            float y = osm[(b * 2000 + m) * 4 + 1];
            float d2 = x * x + y * y;
            key = ((u64)__float_as_uint(d2) << 32) | (u32)m;
        } else key = ~0ull;
        s[m] = key;
    }
    bool lastBig = true;
    for (int k = 2; k <= 2048; k <<= 1) {
        for (int j = k >> 1; j > 0; j >>= 1) {
            bool big = (j >= 64);
            if (big || lastBig) __syncthreads(); else __syncwarp();
            int i0 = ((t & ~(j - 1)) << 1) | (t & (j - 1));
            int i1 = i0 | j;
            bool up = ((i0 & k) == 0);
            u64 A = s[i0], B = s[i1];
            if ((A > B) == up) { s[i0] = B; s[i1] = A; }
            lastBig = big;
        }
    }
    __syncthreads();
    if (t < 1000) {
        u32 m = (u32)(s[t] & 0xffffffffull);
        g_pts[(b * 1000 + t) * 2]     = osm[(b * 2000 + m) * 4];
        g_pts[(b * 1000 + t) * 2 + 1] = osm[(b * 2000 + m) * 4 + 1];
    }
}

// ---------------- K2: per-point MLP, fragment-native, fp16 3-term k16 GEMM ----------------
#define W4STR 66
#define MLP_DSMEM (16 * W4STR * 16)

#define T_PRE_OX 0
#define T_OXX    1
#define T_OXY    2
#define T_OXG    3
#define T_OXBE   4
#define T_W2A    5
#define T_W2B    6
#define T_PRE_TP 7
#define T_TPX    8
#define T_TPY    9
#define T_G1     10
#define T_BE1    11

__global__ void __launch_bounds__(256, 3) mlp_kernel(
    const float* __restrict__ ox_w1, const float* __restrict__ ox_g1, const float* __restrict__ ox_be1,
    const float* __restrict__ ox_w2, const float* __restrict__ ox_b2,
    const float* __restrict__ tp_w1, const float* __restrict__ tp_g1, const float* __restrict__ tp_be1,
    const float* __restrict__ tp_w2, const float* __restrict__ tp_b2,
    const float* __restrict__ tp_g2, const float* __restrict__ tp_be2,
    const float* __restrict__ tp_w3, const float* __restrict__ tp_b3,
    const float* __restrict__ end) {
    extern __shared__ uint4 w4[];
    __shared__ __align__(16) float P[12][64];
    __shared__ __align__(16) float s_b2[64], s_g2[64], s_be2[64], s_w3[128];
    __shared__ float s_red[256];
    __shared__ float s_sc[8];   // linearized LN-mean scalars

    int b = blockIdx.y;
    int tid = threadIdx.x;
    int wid = tid >> 5, lane = tid & 31;

    if (tid < 64) {
        P[T_PRE_OX][tid] = g_pre_ox[b * 64 + tid];
        P[T_PRE_TP][tid] = g_pre_tp[b * 64 + tid];
        P[T_OXX][tid] = ox_w1[128 * 64 + tid];
        P[T_OXY][tid] = ox_w1[129 * 64 + tid];
        P[T_TPX][tid] = tp_w1[128 * 64 + tid];
        P[T_TPY][tid] = tp_w1[129 * 64 + tid];
        P[T_OXG][tid] = ox_g1[tid];
        P[T_OXBE][tid] = ox_be1[tid];
        P[T_G1][tid] = tp_g1[tid];
        P[T_BE1][tid] = tp_be1[tid];
        P[T_W2A][tid] = ox_w2[2 * tid];
        P[T_W2B][tid] = ox_w2[2 * tid + 1];
        s_b2[tid] = tp_b2[tid]; s_g2[tid] = tp_g2[tid]; s_be2[tid] = tp_be2[tid];
    }
    if (tid < 128) s_w3[tid] = tp_w3[tid];
    // warp 1: per-batch means of (pre_ox, oxx, oxy, pre_tp, tpx, tpy) from L2
    if (wid == 1) {
        const float* srcs[6] = { &g_pre_ox[b * 64], &ox_w1[128 * 64], &ox_w1[129 * 64],
                                 &g_pre_tp[b * 64], &tp_w1[128 * 64], &tp_w1[129 * 64] };
#pragma unroll
        for (int q = 0; q < 6; q++) {
            float v = srcs[q][2 * lane] + srcs[q][2 * lane + 1];
            v = wsum(v);
            if (lane == 0) s_sc[q] = v * 0.015625f;
        }
    }
    // W2 -> fp16 hi/lo fragments in b-frag layout
    for (int i = tid; i < 2048; i += 256) {
        int kp = i >> 6, n = i & 63;
        float w0 = tp_w2[(2 * kp) * 64 + n];
        float w1 = tp_w2[(2 * kp + 1) * 64 + n];
        __half2 hh = __floats2half2_rn(w0, w1);
        u32 hi = *reinterpret_cast<u32*>(&hh);
        float2 bk = __half22float2(hh);
        __half2 hl = __floats2half2_rn(w0 - bk.x, w1 - bk.y);
        u32 lo = *reinterpret_cast<u32*>(&hl);
        int kt = kp >> 3, rem = kp & 7;
        int row = kt * 4 + (rem & 3);
        int second = rem >> 2;
        u32* base = reinterpret_cast<u32*>(&w4[row * W4STR + n]);
        base[second]     = hi;
        base[2 + second] = lo;
    }
    __syncthreads();

    int gid = lane >> 2, tig = lane & 3;
    float ex = end[2 * b], ey = end[2 * b + 1];
    float b2o0 = ox_b2[0], b2o1 = ox_b2[1];
    float b3_0 = tp_b3[0], b3_1 = tp_b3[1];
    float mo_p = s_sc[0], mo_x = s_sc[1], mo_y = s_sc[2];
    float mt_p = s_sc[3], mt_x = s_sc[4], mt_y = s_sc[5];
    float smAcc = 0.f;

#pragma unroll 1
    for (int mt = 0; mt < 2; mt++) {
        int iA = blockIdx.x * 256 + wid * 32 + mt * 16 + gid;
        int iB = iA + 8;
        float xA = 0.f, yA = 0.f, xB = 0.f, yB = 0.f;
        if (iA < 1000) { float2 v = *reinterpret_cast<const float2*>(&g_pts[(b * 1000 + iA) * 2]); xA = v.x; yA = v.y; }
        if (iB < 1000) { float2 v = *reinterpret_cast<const float2*>(&g_pts[(b * 1000 + iB) * 2]); xB = v.x; yB = v.y; }

        u64 hA[8], hB[8];
        // layer1-ox (+ linearized means)
        {
            u64 xA2 = F2(xA, xA), yA2 = F2(yA, yA), xB2 = F2(xB, xB), yB2 = F2(yB, yB);
#pragma unroll
            for (int j = 0; j < 8; j++) {
                int o = 8 * j + 2 * tig;
                u64 pre = LD2(&P[T_PRE_OX][o]), wx = LD2(&P[T_OXX][o]), wy = LD2(&P[T_OXY][o]);
                hA[j] = FMA2(yA2, wy, FMA2(xA2, wx, pre));
                hB[j] = FMA2(yB2, wy, FMA2(xB2, wx, pre));
            }
        }
        ln_gelu_frag_m(hA, hB,
                       fmaf(yA, mo_y, fmaf(xA, mo_x, mo_p)),
                       fmaf(yB, mo_y, fmaf(xB, mo_x, mo_p)),
                       &P[T_OXG][0], &P[T_OXBE][0], tig);

        // offset head
        float txA, tyA, txB, tyB;
        {
            u64 axA = F2(0.f, 0.f), ayA = axA, axB = axA, ayB = axA;
#pragma unroll
            for (int j = 0; j < 8; j++) {
                int o = 8 * j + 2 * tig;
                u64 wa = LD2(&P[T_W2A][o]), wb = LD2(&P[T_W2B][o]);
                axA = FMA2(hA[j], wa, axA); ayA = FMA2(hA[j], wb, ayA);
                axB = FMA2(hB[j], wa, axB); ayB = FMA2(hB[j], wb, ayB);
            }
            float p0, p1;
            UNPK(axA, p0, p1); txA = xA + qsum(p0 + p1) + b2o0;
            UNPK(ayA, p0, p1); tyA = yA + qsum(p0 + p1) + b2o1;
            UNPK(axB, p0, p1); txB = xB + qsum(p0 + p1) + b2o0;
            UNPK(ayB, p0, p1); tyB = yB + qsum(p0 + p1) + b2o1;
        }

        // layer1-tp (+ linearized means)
        {
            u64 xA2 = F2(txA, txA), yA2 = F2(tyA, tyA), xB2 = F2(txB, txB), yB2 = F2(tyB, tyB);
#pragma unroll
            for (int j = 0; j < 8; j++) {
                int o = 8 * j + 2 * tig;
                u64 pre = LD2(&P[T_PRE_TP][o]), wx = LD2(&P[T_TPX][o]), wy = LD2(&P[T_TPY][o]);
                hA[j] = FMA2(yA2, wy, FMA2(xA2, wx, pre));
                hB[j] = FMA2(yB2, wy, FMA2(xB2, wx, pre));
            }
        }
        ln_gelu_frag_m(hA, hB,
                       fmaf(tyA, mt_y, fmaf(txA, mt_x, mt_p)),
                       fmaf(tyB, mt_y, fmaf(txB, mt_x, mt_p)),
                       &P[T_G1][0], &P[T_BE1][0], tig);

        // GEMM: 16x64 @ 64x64, fp16 3-term, k16 MMA
        float cst[8][4];
#pragma unroll
        for (int nt = 0; nt < 8; nt++)
#pragma unroll
            for (int qq = 0; qq < 4; qq++) cst[nt][qq] = 0.f;

#pragma unroll
        for (int kt = 0; kt < 4; kt++) {
            u32 ah[4], al[4];
            hsplit(hA[2 * kt],     ah[0], al[0]);
            hsplit(hB[2 * kt],     ah[1], al[1]);
            hsplit(hA[2 * kt + 1], ah[2], al[2]);
            hsplit(hB[2 * kt + 1], ah[3], al[3]);
            const uint4* rp = &w4[(kt * 4 + tig) * W4STR];
#pragma unroll
            for (int nt = 0; nt < 8; nt++) {
                uint4 w = rp[8 * nt + gid];
                mma16f(cst[nt], ah, w.x, w.y);
                mma16f(cst[nt], al, w.x, w.y);
                mma16f(cst[nt], ah, w.z, w.w);
            }
        }

        // epilogue: packed +bias, LN, GELU, 64->2
        u64 cA[8], cB[8];
#pragma unroll
        for (int nt = 0; nt < 8; nt++) {
            int col0 = nt * 8 + 2 * tig;
            u64 b2p = LD2(&s_b2[col0]);
            cA[nt] = ADD2(F2(cst[nt][0], cst[nt][1]), b2p);
            cB[nt] = ADD2(F2(cst[nt][2], cst[nt][3]), b2p);
        }
        u64 sa = cA[0], sb = cB[0];
#pragma unroll
        for (int nt = 1; nt < 8; nt++) { sa = ADD2(sa, cA[nt]); sb = ADD2(sb, cB[nt]); }
        float s0, s1;
        UNPK(sa, s0, s1); float mA = qsum(s0 + s1) * 0.015625f;
        UNPK(sb, s0, s1); float mB = qsum(s0 + s1) * 0.015625f;
        u64 mA2 = F2(-mA, -mA), mB2 = F2(-mB, -mB);
        u64 qa = F2(0.f, 0.f), qb = F2(0.f, 0.f);
#pragma unroll
        for (int nt = 0; nt < 8; nt++) {
            cA[nt] = ADD2(cA[nt], mA2); qa = FMA2(cA[nt], cA[nt], qa);
            cB[nt] = ADD2(cB[nt], mB2); qb = FMA2(cB[nt], cB[nt], qb);
        }
        UNPK(qa, s0, s1); float rA = rsqrtf(qsum(s0 + s1) * 0.015625f + 1e-5f);
        UNPK(qb, s0, s1); float rB = rsqrtf(qsum(s0 + s1) * 0.015625f + 1e-5f);
        u64 rA2 = F2(rA, rA), rB2 = F2(rB, rB);

        u64 accA = F2(0.f, 0.f), accB = F2(0.f, 0.f);
#pragma unroll
        for (int nt = 0; nt < 8; nt++) {
            int col0 = nt * 8 + 2 * tig;
            u64 g2 = LD2(&s_g2[col0]), be2 = LD2(&s_be2[col0]);
            u64 zA = fast_gelu2(FMA2(MUL2(cA[nt], rA2), g2, be2));
            u64 zB = fast_gelu2(FMA2(MUL2(cB[nt], rB2), g2, be2));
            float z0, z1;
            UNPK(zA, z0, z1);
            accA = FMA2(F2(z0, z0), LD2(&s_w3[2 * col0]), accA);
            accA = FMA2(F2(z1, z1), LD2(&s_w3[2 * col0 + 2]), accA);
            UNPK(zB, z0, z1);
            accB = FMA2(F2(z0, z0), LD2(&s_w3[2 * col0]), accB);
            accB = FMA2(F2(z1, z1), LD2(&s_w3[2 * col0 + 2]), accB);
        }
        float px, py;
        UNPK(accA, px, py); float pA0 = qsum(px), pA1 = qsum(py);
        UNPK(accB, px, py); float pB0 = qsum(px), pB1 = qsum(py);

        if (tig == 0) {
            float tA0 = pA0 + b3_0, tA1 = pA1 + b3_1;
            float tB0 = pB0 + b3_0, tB1 = pB1 + b3_1;
            if (iA < 1000) {
                g_targets[(b * 1000 + iA) * 2]     = tA0;
                g_targets[(b * 1000 + iA) * 2 + 1] = tA1;
                smAcc += sl1(tA0 - ex) + sl1(tA1 - ey);
            }
            if (iB < 1000) {
                g_targets[(b * 1000 + iB) * 2]     = tB0;
                g_targets[(b * 1000 + iB) * 2 + 1] = tB1;
                smAcc += sl1(tB0 - ex) + sl1(tB1 - ey);
            }
        }
    }

    s_red[tid] = smAcc;
    __syncthreads();
#pragma unroll
    for (int s = 128; s > 0; s >>= 1) {
        if (tid < s) s_red[tid] += s_red[tid + s];
        __syncthreads();
    }
    if (tid == 0) g_off_part[b * 4 + blockIdx.x] = s_red[0];
}

// ---------------- K3: per-batch stats, policy, top-50 (warp bitonic top-k) ----------------
__global__ void __launch_bounds__(512) finalize_kernel(const float* __restrict__ end,
                                                       float* __restrict__ out) {
    __shared__ float s_t[2000];
    __shared__ float s_p[2000];
    __shared__ float s_pd[1024];
    __shared__ u64 s_key[1024];
    __shared__ float s_w[32];
    __shared__ int   s_wi[16];
    __shared__ float s_bc[8];
    __shared__ int s_bi;

    int b = blockIdx.x, tid = threadIdx.x;
    int wid = tid >> 5, lane = tid & 31;

    for (int i = tid; i < 2000; i += 512) {
        s_t[i] = g_targets[b * 2000 + i];
        s_p[i] = g_pts[b * 2000 + i];
    }
    __syncthreads();

    // mean
    float a0 = 0.f, a1 = 0.f;
    for (int i = tid; i < 1000; i += 512) { a0 += s_t[2 * i]; a1 += s_t[2 * i + 1]; }
    a0 = wsum(a0); a1 = wsum(a1);
    if (lane == 0) { s_w[wid] = a0; s_w[16 + wid] = a1; }
    __syncthreads();
    if (tid < 32) {
        float v = s_w[tid];
        v += __shfl_xor_sync(0xffffffffu, v, 8);
        v += __shfl_xor_sync(0xffffffffu, v, 4);
        v += __shfl_xor_sync(0xffffffffu, v, 2);
        v += __shfl_xor_sync(0xffffffffu, v, 1);
        if ((tid & 15) == 0) s_bc[tid >> 4] = v * 0.001f;
    }
    __syncthreads();
    float m0 = s_bc[0], m1 = s_bc[1];

    // var (ddof=1)
    float q0 = 0.f, q1 = 0.f;
    for (int i = tid; i < 1000; i += 512) {
        float d0 = s_t[2 * i] - m0, d1 = s_t[2 * i + 1] - m1;
        q0 += d0 * d0; q1 += d1 * d1;
    }
    q0 = wsum(q0); q1 = wsum(q1);
    if (lane == 0) { s_w[wid] = q0; s_w[16 + wid] = q1; }
    __syncthreads();
    if (tid < 32) {
        float v = s_w[tid];
        v += __shfl_xor_sync(0xffffffffu, v, 8);
        v += __shfl_xor_sync(0xffffffffu, v, 4);
        v += __shfl_xor_sync(0xffffffffu, v, 2);
        v += __shfl_xor_sync(0xffffffffu, v, 1);
        if ((tid & 15) == 0) s_bc[2 + (tid >> 4)] = v / 999.0f;
    }
    __syncthreads();
    float v0 = s_bc[2], v1 = s_bc[3];

    // policy_dist
    float den0 = sqrtf(6.2831853071795864f * v0 + 1e-6f);
    float den1 = sqrtf(6.2831853071795864f * v1 + 1e-6f);
    for (int i = tid; i < 1024; i += 512) {
        float pd = -1.0f;
        if (i < 1000) {
            float dx = s_t[2 * i] - m0, dy = s_t[2 * i + 1] - m1;
            float pdx = expf(-0.5f * dx * dx / v0 + 1e-6f) / den0;
            float pdy = expf(-0.5f * dy * dy / v1 + 1e-6f) / den1;
            pd = pdx * pdy;
        }
        s_pd[i] = pd;
    }
    __syncthreads();

    // max(pd)
    float mx = -1.0f;
    for (int i = tid; i < 1000; i += 512) mx = fmaxf(mx, s_pd[i]);
#pragma unroll
    for (int o = 16; o; o >>= 1) mx = fmaxf(mx, __shfl_xor_sync(0xffffffffu, mx, o));
    if (lane == 0) s_w[wid] = mx;
    __syncthreads();
    if (tid < 32) {
        float v = (tid < 16) ? s_w[tid] : -3.4e38f;
        v = fmaxf(v, __shfl_xor_sync(0xffffffffu, v, 8));
        v = fmaxf(v, __shfl_xor_sync(0xffffffffu, v, 4));
        v = fmaxf(v, __shfl_xor_sync(0xffffffffu, v, 2));
        v = fmaxf(v, __shfl_xor_sync(0xffffffffu, v, 1));
        if (tid == 0) s_bc[4] = v;
    }
    __syncthreads();
    mx = s_bc[4];

    // sum exp(pd - mx)
    float se = 0.f;
    for (int i = tid; i < 1000; i += 512) se += expf(s_pd[i] - mx);
    se = wsum(se);
    if (lane == 0) s_w[wid] = se;
    __syncthreads();
    if (tid < 32) {
        float v = (tid < 16) ? s_w[tid] : 0.0f;
        v += __shfl_xor_sync(0xffffffffu, v, 8);
        v += __shfl_xor_sync(0xffffffffu, v, 4);
        v += __shfl_xor_sync(0xffffffffu, v, 2);
        v += __shfl_xor_sync(0xffffffffu, v, 1);
        if (tid == 0) s_bc[5] = v;
    }
    __syncthreads();
    float lse = mx + logf(s_bc[5]);

    // argmin distance to end (first-index tiebreak)
    float ex = end[2 * b], ey = end[2 * b + 1];
    float bd = 3.4e38f; int bi = 0x7fffffff;
    for (int i = tid; i < 1000; i += 512) {
        float dx = s_p[2 * i] - ex;
        float dy = s_p[2 * i + 1] - ey;
        float ds = sqrtf(dx * dx + dy * dy);
        if (ds < bd || (ds == bd && i < bi)) { bd = ds; bi = i; }
    }
#pragma unroll
    for (int o = 16; o; o >>= 1) {
        float od = __shfl_xor_sync(0xffffffffu, bd, o);
        int   oi = __shfl_xor_sync(0xffffffffu, bi, o);
        if (od < bd || (od == bd && oi < bi)) { bd = od; bi = oi; }
    }
    if (lane == 0) { s_w[wid] = bd; s_wi[wid] = bi; }
    __syncthreads();
    if (tid < 32) {
        float v  = (tid < 16) ? s_w[tid]  : 3.4e38f;
        int   vi = (tid < 16) ? s_wi[tid] : 0x7fffffff;
#pragma unroll
        for (int o = 8; o; o >>= 1) {
            float od = __shfl_xor_sync(0xffffffffu, v, o);
            int   oi = __shfl_xor_sync(0xffffffffu, vi, o);
            if (od < v || (od == v && oi < vi)) { v = od; vi = oi; }
        }
        if (tid == 0) s_bi = vi;
    }
    __syncthreads();
    float picked = s_pd[s_bi];

    // ---- top-50: warp-register bitonic top-k ----
    u64 k0, k1;
    {
        int i0 = wid * 64 + lane, i1 = i0 + 32;
        k0 = (i0 < 1000) ? ((((u64)__float_as_uint(s_pd[i0])) << 32) | (u32)(~i0)) : 0ull;
        k1 = (i1 < 1000) ? ((((u64)__float_as_uint(s_pd[i1])) << 32) | (u32)(~i1)) : 0ull;
    }
#pragma unroll
    for (int k = 2; k <= 64; k <<= 1) {
#pragma unroll
        for (int j = k >> 1; j > 0; j >>= 1) {
            if (j == 32) {
                u64 mxk = k0 > k1 ? k0 : k1;
                u64 mnk = k0 > k1 ? k1 : k0;
                k0 = mxk; k1 = mnk;
            } else {
                u64 o0 = __shfl_xor_sync(0xffffffffu, k0, j);
                u64 o1 = __shfl_xor_sync(0xffffffffu, k1, j);
                bool low = (lane & j) == 0;
                bool d0 = (lane & k) == 0;
                bool d1 = (((lane + 32) & k) == 0);
                bool t0 = (low == d0), t1 = (low == d1);
                k0 = t0 ? (k0 > o0 ? k0 : o0) : (k0 < o0 ? k0 : o0);
                k1 = t1 ? (k1 > o1 ? k1 : o1) : (k1 < o1 ? k1 : o1);
            }
        }
    }
    s_key[wid * 64 + lane] = k0;
    s_key[wid * 64 + 32 + lane] = k1;
    __syncthreads();
#pragma unroll
    for (int act = 8; act >= 1; act >>= 1) {
        if (wid < act) {
            u64 a0k = s_key[(2 * wid) * 64 + lane];
            u64 a1k = s_key[(2 * wid) * 64 + 32 + lane];
            u64 b0k = s_key[(2 * wid + 1) * 64 + 63 - lane];
            u64 b1k = s_key[(2 * wid + 1) * 64 + 31 - lane];
            k0 = a0k > b0k ? a0k : b0k;
            k1 = a1k > b1k ? a1k : b1k;
            { u64 mxk = k0 > k1 ? k0 : k1, mnk = k0 > k1 ? k1 : k0; k0 = mxk; k1 = mnk; }
#pragma unroll
            for (int j = 16; j > 0; j >>= 1) {
                u64 o0 = __shfl_xor_sync(0xffffffffu, k0, j);
                u64 o1 = __shfl_xor_sync(0xffffffffu, k1, j);
                bool tm = (lane & j) == 0;
                k0 = tm ? (k0 > o0 ? k0 : o0) : (k0 < o0 ? k0 : o0);
                k1 = tm ? (k1 > o1 ? k1 : o1) : (k1 < o1 ? k1 : o1);
            }
        }
        __syncthreads();
        if (act > 1 && wid < act) {
            s_key[wid * 64 + lane] = k0;
            s_key[wid * 64 + 32 + lane] = k1;
        }
        __syncthreads();
    }

    if (wid == 0) {
        float es = 0.f;
        u32 id = ~(u32)k0;
        float t0 = s_t[2 * id], t1 = s_t[2 * id + 1];
        out[2 + (b * 50 + lane) * 2]     = t0;
        out[2 + (b * 50 + lane) * 2 + 1] = t1;
        es = sl1(t0 - ex) + sl1(t1 - ey);
        if (lane < 18) {
            u32 id2 = ~(u32)k1;
            float u0 = s_t[2 * id2], u1 = s_t[2 * id2 + 1];
            int pos = 32 + lane;
            out[2 + (b * 50 + pos) * 2]     = u0;
            out[2 + (b * 50 + pos) * 2 + 1] = u1;
            es += sl1(u0 - ex) + sl1(u1 - ey);
        }
        es = wsum(es);
        if (lane == 0) {
            g_cls[b] = lse - picked;
            g_endsum[b] = es;
        }
    }
}

// ---------------- K4: final scalar reductions ----------------
__global__ void __launch_bounds__(512) reduce_kernel(float* __restrict__ out) {
    __shared__ float r[512];
    int tid = threadIdx.x;
    float offs = 0.f;
    for (int i = tid; i < 2048; i += 512) offs += g_off_part[i];
    float cls = g_cls[tid];
    float ends = g_endsum[tid];

    r[tid] = offs; __syncthreads();
    for (int s = 256; s > 0; s >>= 1) { if (tid < s) r[tid] += r[tid + s]; __syncthreads(); }
    float offT = r[0]; __syncthreads();
    r[tid] = cls; __syncthreads();
    for (int s = 256; s > 0; s >>= 1) { if (tid < s) r[tid] += r[tid + s]; __syncthreads(); }
    float clsT = r[0]; __syncthreads();
    r[tid] = ends; __syncthreads();
    for (int s = 256; s > 0; s >>= 1) { if (tid < s) r[tid] += r[tid + s]; __syncthreads(); }
    float endT = r[0];

    if (tid == 0) {
        out[0] = clsT / 512.0f;
        out[1] = offT / 1024000.0f + 3.0f * (endT / 51200.0f);
    }
}

extern "C" void kernel_launch(void* const* d_in, const int* in_sizes, int n_in,
                              void* d_out, int out_size) {
    const float* osm   = (const float*)d_in[0];
    const float* at    = (const float*)d_in[1];
    const float* vf    = (const float*)d_in[2];
    const float* end   = (const float*)d_in[3];
    const float* ox_w1 = (const float*)d_in[5];
    const float* ox_b1 = (const float*)d_in[6];
    const float* ox_g1 = (const float*)d_in[7];
    const float* ox_be1= (const float*)d_in[8];
    const float* ox_w2 = (const float*)d_in[9];
    const float* ox_b2 = (const float*)d_in[10];
    const float* tp_w1 = (const float*)d_in[11];
    const float* tp_b1 = (const float*)d_in[12];
    const float* tp_g1 = (const float*)d_in[13];
    const float* tp_be1= (const float*)d_in[14];
    const float* tp_w2 = (const float*)d_in[15];
    const float* tp_b2 = (const float*)d_in[16];
    const float* tp_g2 = (const float*)d_in[17];
    const float* tp_be2= (const float*)d_in[18];
    const float* tp_w3 = (const float*)d_in[19];
    const float* tp_b3 = (const float*)d_in[20];
    float* out = (float*)d_out;

    prof_pad_kernel<<<1, 32>>>();   // keeps ncu capture slot on mlp_kernel
    precompute_kernel<<<512, 256>>>(at, vf, ox_w1, ox_b1, tp_w1, tp_b1);
    select_kernel<<<512, 1024>>>(osm);
    dim3 g(4, 512);
    mlp_kernel<<<g, 256, MLP_DSMEM>>>(ox_w1, ox_g1, ox_be1, ox_w2, ox_b2,
                                      tp_w1, tp_g1, tp_be1, tp_w2, tp_b2,
                                      tp_g2, tp_be2, tp_w3, tp_b3, end);
    finalize_kernel<<<512, 512>>>(end, out);
    reduce_kernel<<<1, 512>>>(out);
}